// round 12
// baseline (speedup 1.0000x reference)
#include <cuda_runtime.h>
#include <cuda.h>
#include <cuda_fp16.h>
#include <math.h>

#define BB 8
#define CC 256
#define NN 16384
#define HEADS 8
#define INNER 512
#define KCONV 2304
#define KRR 64
#define DHH 64

__device__ __half g_wch[(size_t)INNER * KCONV];
__device__ __half g_xh[(size_t)BB * NN * CC];
__device__ __half g_w1h[CC * INNER];
__device__ __half g_w2h[CC * CC];
__device__ __half g_xc[(size_t)BB * NN * INNER];
__device__ float  g_colsum[BB * HEADS * KRR];
__device__ float  g_kv[BB * HEADS * KRR * DHH];
__device__ __half g_qkv[(size_t)BB * NN * INNER];
__device__ __half g_h1[(size_t)BB * NN * CC];
__device__ __half g_wqh[4096], g_wql[4096], g_wkh[4096], g_wkl[4096];
__device__ __half g_wvh[4096], g_wvl[4096];
__device__ __half g_kvth[64 * 4096], g_kvtl[64 * 4096];   // [bh][dh][kr]

__device__ __forceinline__ void mma_f16(float c[4], const unsigned a[4], const unsigned b[2]) {
    asm volatile("mma.sync.aligned.m16n8k16.row.col.f32.f16.f16.f32 "
        "{%0,%1,%2,%3}, {%4,%5,%6,%7}, {%8,%9}, {%0,%1,%2,%3};"
        : "+f"(c[0]), "+f"(c[1]), "+f"(c[2]), "+f"(c[3])
        : "r"(a[0]), "r"(a[1]), "r"(a[2]), "r"(a[3]), "r"(b[0]), "r"(b[1]));
}
__device__ __forceinline__ void lm4(unsigned r[4], unsigned a) {
    asm volatile("ldmatrix.sync.aligned.m8n8.x4.shared.b16 {%0,%1,%2,%3}, [%4];"
        : "=r"(r[0]), "=r"(r[1]), "=r"(r[2]), "=r"(r[3]) : "r"(a));
}
__device__ __forceinline__ void split_h(float f, __half& hi, __half& lo) {
    hi = __float2half_rn(f);
    lo = __float2half_rn(f - __half2float(hi));
}
__device__ __forceinline__ unsigned smem_u32(const void* p) {
    return (unsigned)__cvta_generic_to_shared(p);
}
__device__ __forceinline__ void mb_init(unsigned a, unsigned n) {
    asm volatile("mbarrier.init.shared.b64 [%0], %1;" :: "r"(a), "r"(n) : "memory");
}
__device__ __forceinline__ void mb_expect(unsigned a, unsigned bytes) {
    asm volatile("mbarrier.arrive.expect_tx.shared.b64 _, [%0], %1;"
                 :: "r"(a), "r"(bytes) : "memory");
}
__device__ __forceinline__ void mb_wait(unsigned a, unsigned ph) {
    asm volatile("{\n\t.reg .pred P;\n\tW%=:\n\t"
                 "mbarrier.try_wait.parity.shared.b64 P, [%0], %1;\n\t"
                 "@!P bra W%=;\n\t}" :: "r"(a), "r"(ph) : "memory");
}
__device__ __forceinline__ void tma4d(unsigned dst, const CUtensorMap* m,
                                      int c0, int c1, int c2, int c3, unsigned mb) {
    asm volatile("cp.async.bulk.tensor.4d.shared::cta.global.tile.mbarrier::complete_tx::bytes"
                 " [%0], [%1, {%2,%3,%4,%5}], [%6];"
                 :: "r"(dst), "l"(m), "r"(c0), "r"(c1), "r"(c2), "r"(c3), "r"(mb) : "memory");
}
__device__ __forceinline__ void tma2d(unsigned dst, const CUtensorMap* m,
                                      int c0, int c1, unsigned mb) {
    asm volatile("cp.async.bulk.tensor.2d.shared::cta.global.tile.mbarrier::complete_tx::bytes"
                 " [%0], [%1, {%2,%3}], [%4];"
                 :: "r"(dst), "l"(m), "r"(c0), "r"(c1), "r"(mb) : "memory");
}

// ---------------- prep ---------------------------------------------------------
__global__ void k_wprep(const float* __restrict__ conv_w) {
    int t = blockIdx.x * 256 + threadIdx.x;
    if (t >= INNER * KCONV) return;
    int o = t / KCONV, k = t - o * KCONV;
    g_wch[t] = __float2half_rn(conv_w[(size_t)(o * CC + (k & 255)) * 9 + (k >> 8)]);
}
__global__ void k_xprep(const float* __restrict__ x) {
    int t = blockIdx.x * 256 + threadIdx.x;
    float4 v = ((const float4*)x)[t];
    ((__half2*)g_xh)[t * 2]     = __floats2half2_rn(v.x, v.y);
    ((__half2*)g_xh)[t * 2 + 1] = __floats2half2_rn(v.z, v.w);
}
// fused: W1/W2 halve + Wq/Wk/Wv splits + kv/colsum zero-init
__global__ void k_prep2(const float* __restrict__ W1, const float* __restrict__ W2,
                        const float* __restrict__ Wq, const float* __restrict__ Wk,
                        const float* __restrict__ Wv) {
    int t = blockIdx.x * 256 + threadIdx.x;            // 262144
    g_kv[t] = 0.f;
    if (t < CC * INNER) g_w1h[t] = __float2half_rn(W1[t]);
    if (t < CC * CC)    g_w2h[t] = __float2half_rn(W2[t]);
    if (t < BB * HEADS * KRR) g_colsum[t] = 0.f;
    if (t < 4096) {
        split_h(Wq[t], g_wqh[t], g_wql[t]);
        split_h(Wk[t], g_wkh[t], g_wkl[t]);
        split_h(Wv[t], g_wvh[t], g_wvl[t]);
    }
}

// ---------------- conv: fp16 mma + ldmatrix, TMA 3-buffer ring ------------------
// smem: [0..1024) mbarriers; A bufs @1024 (3x16K); B bufs @50176 (3x16K); 99328 B
__global__ __launch_bounds__(256) void k_conv(
    const __grid_constant__ CUtensorMap mA,
    const __grid_constant__ CUtensorMap mB,
    const float* __restrict__ conv_b) {
    extern __shared__ __align__(1024) char smc[];
    const unsigned sbase = smem_u32(smc);
    const int tid = threadIdx.x, lane = tid & 31, wid = tid >> 5;
    const int wm = wid & 3, wn = wid >> 2;
    const int grp = lane >> 2, tig = lane & 3;
    const int otile = blockIdx.x * 128, mtile = blockIdx.y * 128;
    const int b = mtile >> 14;
    const int py = (mtile & (NN - 1)) >> 7;

    if (tid == 0) { mb_init(sbase, 1); mb_init(sbase + 8, 1); mb_init(sbase + 16, 1); }
    __syncthreads();

    const int a_r = (lane & 7) + ((lane >> 3) & 1) * 8;
    const unsigned a_kb = (lane >> 4) * 16;
    const unsigned axor = (unsigned)(a_r & 7) << 4;
    const int b_r = (lane & 7) + (lane >> 4) * 8;
    const unsigned b_kb = ((lane >> 3) & 1) * 16;
    const unsigned bxor = (unsigned)(b_r & 7) << 4;
    const unsigned Abase0 = sbase + 1024;
    const unsigned Bbase0 = sbase + 50176;

    float acc[2][8][4] = {};

    auto issue = [&](int s) {
        const int p = s % 3;
        const int g = s >> 2;
        const int dy = g / 3 - 1, dx = g % 3 - 1;
        const int cb = (s & 3) * 64;
        mb_expect(sbase + p * 8, 32768);
        tma4d(Abase0 + p * 16384, &mA, cb, dx, py + dy, b, sbase + p * 8);
        tma2d(Bbase0 + p * 16384, &mB, g * 256 + cb, otile, sbase + p * 8);
    };

    if (tid == 0) { issue(0); issue(1); }
    for (int s = 0; s < 36; s++) {
        const int p = s % 3;
        if (s + 2 < 36 && tid == 0) issue(s + 2);
        mb_wait(sbase + p * 8, (s / 3) & 1);
        const unsigned Ab = Abase0 + p * 16384;
        const unsigned Bb = Bbase0 + p * 16384;
        #pragma unroll
        for (int ks = 0; ks < 4; ks++) {
            const unsigned ak = ((unsigned)(ks * 32) + a_kb) ^ axor;
            const unsigned bk = ((unsigned)(ks * 32) + b_kb) ^ bxor;
            unsigned a0[4], a1[4];
            lm4(a0, Ab + (unsigned)(wm * 32 + a_r) * 128 + ak);
            lm4(a1, Ab + (unsigned)(wm * 32 + 16 + a_r) * 128 + ak);
            #pragma unroll
            for (int np = 0; np < 4; np++) {
                unsigned bb[4];
                lm4(bb, Bb + (unsigned)(wn * 64 + np * 16 + b_r) * 128 + bk);
                mma_f16(acc[0][np * 2],     a0, bb);
                mma_f16(acc[1][np * 2],     a1, bb);
                mma_f16(acc[0][np * 2 + 1], a0, bb + 2);
                mma_f16(acc[1][np * 2 + 1], a1, bb + 2);
            }
        }
        __syncthreads();
    }
    #pragma unroll
    for (int mt = 0; mt < 2; mt++)
        #pragma unroll
        for (int nt = 0; nt < 8; nt++) {
            const int r = wm * 32 + mt * 16 + grp;
            const int c = wn * 64 + nt * 8 + tig * 2;
            const float b0 = conv_b[otile + c], b1 = conv_b[otile + c + 1];
            *(__half2*)(g_xc + (size_t)(mtile + r) * INNER + otile + c) =
                __floats2half2_rn(acc[mt][nt][0] + b0, acc[mt][nt][1] + b1);
            *(__half2*)(g_xc + (size_t)(mtile + r + 8) * INNER + otile + c) =
                __floats2half2_rn(acc[mt][nt][2] + b0, acc[mt][nt][3] + b1);
        }
}

// ---------------- MLP: fp16 mma + ldmatrix, TMA 3-buffer ring -------------------
template <int MODE>
__global__ __launch_bounds__(256) void k_mlp(
    const __grid_constant__ CUtensorMap mA,
    const __grid_constant__ CUtensorMap mB,
    const float* __restrict__ bias,
    float* __restrict__ out_ext) {
    constexpr int K = MODE ? CC : INNER;
    constexpr int NS = K / 64;
    extern __shared__ __align__(1024) char smc[];
    const unsigned sbase = smem_u32(smc);
    const int tid = threadIdx.x, lane = tid & 31, wid = tid >> 5;
    const int wm = wid & 3, wn = wid >> 2;
    const int grp = lane >> 2, tig = lane & 3;
    const int otile = blockIdx.x * 128, m0 = blockIdx.y * 128;

    if (tid == 0) { mb_init(sbase, 1); mb_init(sbase + 8, 1); mb_init(sbase + 16, 1); }
    __syncthreads();

    const int a_r = (lane & 7) + ((lane >> 3) & 1) * 8;
    const unsigned a_kb = (lane >> 4) * 16;
    const unsigned axor = (unsigned)(a_r & 7) << 4;
    const int b_r = (lane & 7) + (lane >> 4) * 8;
    const unsigned b_kb = ((lane >> 3) & 1) * 16;
    const unsigned bxor = (unsigned)(b_r & 7) << 4;
    const unsigned Abase0 = sbase + 1024;
    const unsigned Bbase0 = sbase + 50176;

    float acc[2][8][4] = {};

    auto issue = [&](int s) {
        const int p = s % 3;
        mb_expect(sbase + p * 8, 32768);
        tma2d(Abase0 + p * 16384, &mA, s * 64, m0, sbase + p * 8);
        tma2d(Bbase0 + p * 16384, &mB, s * 64, otile, sbase + p * 8);
    };

    if (tid == 0) { issue(0); if (NS > 1) issue(1); }
    for (int s = 0; s < NS; s++) {
        const int p = s % 3;
        if (s + 2 < NS && tid == 0) issue(s + 2);
        mb_wait(sbase + p * 8, (s / 3) & 1);
        const unsigned Ab = Abase0 + p * 16384;
        const unsigned Bb = Bbase0 + p * 16384;
        #pragma unroll
        for (int ks = 0; ks < 4; ks++) {
            const unsigned ak = ((unsigned)(ks * 32) + a_kb) ^ axor;
            const unsigned bk = ((unsigned)(ks * 32) + b_kb) ^ bxor;
            unsigned a0[4], a1[4];
            lm4(a0, Ab + (unsigned)(wm * 32 + a_r) * 128 + ak);
            lm4(a1, Ab + (unsigned)(wm * 32 + 16 + a_r) * 128 + ak);
            #pragma unroll
            for (int np = 0; np < 4; np++) {
                unsigned bb[4];
                lm4(bb, Bb + (unsigned)(wn * 64 + np * 16 + b_r) * 128 + bk);
                mma_f16(acc[0][np * 2],     a0, bb);
                mma_f16(acc[1][np * 2],     a1, bb);
                mma_f16(acc[0][np * 2 + 1], a0, bb + 2);
                mma_f16(acc[1][np * 2 + 1], a1, bb + 2);
            }
        }
        __syncthreads();
    }
    #pragma unroll
    for (int mt = 0; mt < 2; mt++)
        #pragma unroll
        for (int nt = 0; nt < 8; nt++) {
            const int r = wm * 32 + mt * 16 + grp;
            const int c = wn * 64 + nt * 8 + tig * 2;
            const float b0 = bias[otile + c], b1 = bias[otile + c + 1];
            float v[4] = {acc[mt][nt][0] + b0, acc[mt][nt][1] + b1,
                          acc[mt][nt][2] + b0, acc[mt][nt][3] + b1};
            if (MODE == 0) {
                #pragma unroll
                for (int j = 0; j < 4; j++)
                    v[j] = 0.5f * v[j] * (1.0f + erff(v[j] * 0.70710678118654752f));
                *(__half2*)(g_h1 + (size_t)(m0 + r) * CC + otile + c) =
                    __floats2half2_rn(v[0], v[1]);
                *(__half2*)(g_h1 + (size_t)(m0 + r + 8) * CC + otile + c) =
                    __floats2half2_rn(v[2], v[3]);
            } else {
                *(float2*)(out_ext + (size_t)(m0 + r) * CC + otile + c) =
                    make_float2(v[0], v[1]);
                *(float2*)(out_ext + (size_t)(m0 + r + 8) * CC + otile + c) =
                    make_float2(v[2], v[3]);
            }
        }
}

// ---------------- k_kv: fp16 split mma, ldmatrix, double-buffered X ------------
__global__ __launch_bounds__(256) void k_kv() {
    extern __shared__ __half sh[];
    __half *Xs0 = sh, *Xs1 = sh + 4608;             // [64][72] x2
    __half *Wkh = sh + 9216,  *Wkl = sh + 13824;
    __half *Wvh = sh + 18432, *Wvl = sh + 23040;
    __half *Kth = sh + 27648, *Ktl = sh + 32256;    // [kr][seq]
    __half *Vth = sh + 36864, *Vtl = sh + 41472;    // [dh][seq]

    const int tid = threadIdx.x, lane = tid & 31, wid = tid >> 5;
    const int wm = wid & 3, wn = wid >> 2;
    const int grp = lane >> 2, tig = lane & 3;
    const int bh = blockIdx.y, b = bh >> 3, h = bh & 7;
    const int r = tid >> 2, c0 = (tid & 3) * 16;

    {
        const int gsrc = r * 64 + c0;
        const int sdst = r * 72 + c0;
        *(uint4*)&Wkh[sdst]     = *(const uint4*)&g_wkh[gsrc];
        *(uint4*)&Wkh[sdst + 8] = *(const uint4*)&g_wkh[gsrc + 8];
        *(uint4*)&Wkl[sdst]     = *(const uint4*)&g_wkl[gsrc];
        *(uint4*)&Wkl[sdst + 8] = *(const uint4*)&g_wkl[gsrc + 8];
        *(uint4*)&Wvh[sdst]     = *(const uint4*)&g_wvh[gsrc];
        *(uint4*)&Wvh[sdst + 8] = *(const uint4*)&g_wvh[gsrc + 8];
        *(uint4*)&Wvl[sdst]     = *(const uint4*)&g_wvl[gsrc];
        *(uint4*)&Wvl[sdst + 8] = *(const uint4*)&g_wvl[gsrc + 8];
    }

    const int la_r = (lane & 7) + ((lane >> 3) & 1) * 8;
    const unsigned a_off = (unsigned)la_r * 144 + (lane >> 4) * 16;
    const int lb_r = (lane & 7) + (lane >> 4) * 8;
    const unsigned b_off = (unsigned)lb_r * 144 + ((lane >> 3) & 1) * 16;
    const unsigned Xs0U = smem_u32(Xs0);
    const unsigned WkhU = smem_u32(Wkh), WklU = smem_u32(Wkl);
    const unsigned WvhU = smem_u32(Wvh), WvlU = smem_u32(Wvl);
    const unsigned KthU = smem_u32(Kth), KtlU = smem_u32(Ktl);
    const unsigned VthU = smem_u32(Vth), VtlU = smem_u32(Vtl);
    const unsigned aTile = (unsigned)(wm * 16) * 144 + a_off;
    const unsigned nb0 = (unsigned)(wn * 32) * 144 + b_off;
    const unsigned nb1 = nb0 + 16u * 144;

    float kvacc[4][4] = {};
    float csum[8] = {};
    const int mrow = wm * 16 + grp;

    for (int ch = 0; ch < 32; ch++) {
        const int n0 = blockIdx.x * 2048 + ch * 64;
        __half* Xc = (ch & 1) ? Xs1 : Xs0;
        {
            const __half* xsrc = g_xc + (size_t)(b * NN + n0 + r) * INNER + h * 64 + c0;
            *(uint4*)&Xc[r * 72 + c0]     = *(const uint4*)xsrc;
            *(uint4*)&Xc[r * 72 + c0 + 8] = *(const uint4*)(xsrc + 8);
        }
        __syncthreads();     // X visible; prev kv-mma done -> Kt/Vt writable

        const unsigned XcU = Xs0U + (unsigned)(ch & 1) * 9216;
        float ka[4][4] = {}, va[4][4] = {};
        #pragma unroll
        for (int ks = 0; ks < 4; ks++) {
            const unsigned kcB = (unsigned)ks * 32;
            unsigned a[4];
            lm4(a, XcU + aTile + kcB);
            unsigned kh0[4], kh1[4], kl0[4], kl1[4];
            unsigned vh0[4], vh1[4], vl0[4], vl1[4];
            lm4(kh0, WkhU + nb0 + kcB); lm4(kh1, WkhU + nb1 + kcB);
            lm4(kl0, WklU + nb0 + kcB); lm4(kl1, WklU + nb1 + kcB);
            lm4(vh0, WvhU + nb0 + kcB); lm4(vh1, WvhU + nb1 + kcB);
            lm4(vl0, WvlU + nb0 + kcB); lm4(vl1, WvlU + nb1 + kcB);
            mma_f16(ka[0], a, kh0);     mma_f16(ka[0], a, kl0);
            mma_f16(ka[1], a, kh0 + 2); mma_f16(ka[1], a, kl0 + 2);
            mma_f16(ka[2], a, kh1);     mma_f16(ka[2], a, kl1);
            mma_f16(ka[3], a, kh1 + 2); mma_f16(ka[3], a, kl1 + 2);
            mma_f16(va[0], a, vh0);     mma_f16(va[0], a, vl0);
            mma_f16(va[1], a, vh0 + 2); mma_f16(va[1], a, vl0 + 2);
            mma_f16(va[2], a, vh1);     mma_f16(va[2], a, vl1);
            mma_f16(va[3], a, vh1 + 2); mma_f16(va[3], a, vl1 + 2);
        }
        #pragma unroll
        for (int nt = 0; nt < 4; nt++) {
            const int c = wn * 32 + nt * 8 + tig * 2;
            float e;
            e = __expf(ka[nt][0]); csum[nt*2]   += e; split_h(e, Kth[c*72+mrow],       Ktl[c*72+mrow]);
            e = __expf(ka[nt][1]); csum[nt*2+1] += e; split_h(e, Kth[(c+1)*72+mrow],   Ktl[(c+1)*72+mrow]);
            e = __expf(ka[nt][2]); csum[nt*2]   += e; split_h(e, Kth[c*72+mrow+8],     Ktl[c*72+mrow+8]);
            e = __expf(ka[nt][3]); csum[nt*2+1] += e; split_h(e, Kth[(c+1)*72+mrow+8], Ktl[(c+1)*72+mrow+8]);
            split_h(va[nt][0], Vth[c*72+mrow],       Vtl[c*72+mrow]);
            split_h(va[nt][1], Vth[(c+1)*72+mrow],   Vtl[(c+1)*72+mrow]);
            split_h(va[nt][2], Vth[c*72+mrow+8],     Vtl[c*72+mrow+8]);
            split_h(va[nt][3], Vth[(c+1)*72+mrow+8], Vtl[(c+1)*72+mrow+8]);
        }
        __syncthreads();     // Kt/Vt visible

        #pragma unroll
        for (int ks = 0; ks < 4; ks++) {
            const unsigned kcB = (unsigned)ks * 32;
            unsigned ah[4], al[4];
            lm4(ah, KthU + aTile + kcB);
            lm4(al, KtlU + aTile + kcB);
            unsigned bh0[4], bh1[4], bl0[4], bl1[4];
            lm4(bh0, VthU + nb0 + kcB); lm4(bh1, VthU + nb1 + kcB);
            lm4(bl0, VtlU + nb0 + kcB); lm4(bl1, VtlU + nb1 + kcB);
            mma_f16(kvacc[0], ah, bh0);     mma_f16(kvacc[0], ah, bl0);     mma_f16(kvacc[0], al, bh0);
            mma_f16(kvacc[1], ah, bh0 + 2); mma_f16(kvacc[1], ah, bl0 + 2); mma_f16(kvacc[1], al, bh0 + 2);
            mma_f16(kvacc[2], ah, bh1);     mma_f16(kvacc[2], ah, bl1);     mma_f16(kvacc[2], al, bh1);
            mma_f16(kvacc[3], ah, bh1 + 2); mma_f16(kvacc[3], ah, bl1 + 2); mma_f16(kvacc[3], al, bh1 + 2);
        }
    }

    float* kvbase = g_kv + (size_t)bh * (KRR * DHH);
    #pragma unroll
    for (int nt = 0; nt < 4; nt++) {
        const int c = wn * 32 + nt * 8 + tig * 2;
        atomicAdd(kvbase + mrow * 64 + c,           kvacc[nt][0]);
        atomicAdd(kvbase + mrow * 64 + c + 1,       kvacc[nt][1]);
        atomicAdd(kvbase + (mrow + 8) * 64 + c,     kvacc[nt][2]);
        atomicAdd(kvbase + (mrow + 8) * 64 + c + 1, kvacc[nt][3]);
    }
    #pragma unroll
    for (int idx = 0; idx < 8; idx++) {
        const int c = wn * 32 + (idx >> 1) * 8 + tig * 2 + (idx & 1);
        atomicAdd(g_colsum + bh * 64 + c, csum[idx]);
    }
}

// ---------------- kv normalize + transpose + split ------------------------------
__global__ void k_kvnorm() {
    int i = blockIdx.x * 256 + threadIdx.x;           // 262144
    float v = g_kv[i] / g_colsum[i >> 6];
    int bh = i >> 12, kr = (i >> 6) & 63, dh = i & 63;
    __half hi, lo;
    split_h(v, hi, lo);
    int o = bh * 4096 + dh * 64 + kr;
    g_kvth[o] = hi;
    g_kvtl[o] = lo;
}

// ---------------- k_qkv: fp16 split mma, ldmatrix fragments ---------------------
__global__ __launch_bounds__(256) void k_qkv() {
    extern __shared__ __half sh[];
    __half *Xs   = sh;                               // [128][72]
    __half *Qh   = sh + 9216,  *Ql  = sh + 18432;    // [128][72]
    __half *Wqh  = sh + 27648, *Wql = sh + 32256;    // [64][72]
    __half *kvth = sh + 36864, *kvtl = sh + 41472;   // [dh][kr]
    float  *rsum = (float*)(sh + 46080);
    float  *inv  = rsum + 128;

    const int tid = threadIdx.x, lane = tid & 31, wid = tid >> 5;
    const int wm = wid & 3, wn = wid >> 2;
    const int grp = lane >> 2, tig = lane & 3;
    const int bh = blockIdx.y, b = bh >> 3, h = bh & 7;
    const int n0 = blockIdx.x * 128;

    if (tid < 128) rsum[tid] = 0.f;
    {
        const int r = tid >> 2, c0 = (tid & 3) * 16;
        const int gsrc = r * 64 + c0;
        const int sdst = r * 72 + c0;
        *(uint4*)&Wqh[sdst]     = *(const uint4*)&g_wqh[gsrc];
        *(uint4*)&Wqh[sdst + 8] = *(const uint4*)&g_wqh[gsrc + 8];
        *(uint4*)&Wql[sdst]     = *(const uint4*)&g_wql[gsrc];
        *(uint4*)&Wql[sdst + 8] = *(const uint4*)&g_wql[gsrc + 8];
        const __half* kvh = g_kvth + bh * 4096 + gsrc;
        const __half* kvl = g_kvtl + bh * 4096 + gsrc;
        *(uint4*)&kvth[sdst]     = *(const uint4*)kvh;
        *(uint4*)&kvth[sdst + 8] = *(const uint4*)(kvh + 8);
        *(uint4*)&kvtl[sdst]     = *(const uint4*)kvl;
        *(uint4*)&kvtl[sdst + 8] = *(const uint4*)(kvl + 8);
    }
    {
        const int xr = tid >> 1, xc0 = (tid & 1) * 32;
        const __half* xsrc = g_xc + (size_t)(b * NN + n0 + xr) * INNER + h * 64 + xc0;
        #pragma unroll
        for (int j = 0; j < 4; j++)
            *(uint4*)&Xs[xr * 72 + xc0 + j * 8] = *(const uint4*)(xsrc + j * 8);
    }
    __syncthreads();

    const int la_r = (lane & 7) + ((lane >> 3) & 1) * 8;
    const unsigned a_off = (unsigned)la_r * 144 + (lane >> 4) * 16;
    const int lb_r = (lane & 7) + (lane >> 4) * 8;
    const unsigned b_off = (unsigned)lb_r * 144 + ((lane >> 3) & 1) * 16;
    const unsigned XsU = smem_u32(Xs), QhU = smem_u32(Qh), QlU = smem_u32(Ql);
    const unsigned WqhU = smem_u32(Wqh), WqlU = smem_u32(Wql);
    const unsigned kvhU = smem_u32(kvth), kvlU = smem_u32(kvtl);
    const unsigned aT0 = (unsigned)(wm * 32) * 144 + a_off;
    const unsigned aT1 = aT0 + 16u * 144;
    const unsigned nb0 = (unsigned)(wn * 32) * 144 + b_off;
    const unsigned nb1 = nb0 + 16u * 144;

    float qa[2][4][4] = {};
    #pragma unroll
    for (int ks = 0; ks < 4; ks++) {
        const unsigned kcB = (unsigned)ks * 32;
        unsigned a0[4], a1[4];
        lm4(a0, XsU + aT0 + kcB);
        lm4(a1, XsU + aT1 + kcB);
        unsigned qh0[4], qh1[4], ql0[4], ql1[4];
        lm4(qh0, WqhU + nb0 + kcB); lm4(qh1, WqhU + nb1 + kcB);
        lm4(ql0, WqlU + nb0 + kcB); lm4(ql1, WqlU + nb1 + kcB);
        mma_f16(qa[0][0], a0, qh0);     mma_f16(qa[0][0], a0, ql0);
        mma_f16(qa[1][0], a1, qh0);     mma_f16(qa[1][0], a1, ql0);
        mma_f16(qa[0][1], a0, qh0 + 2); mma_f16(qa[0][1], a0, ql0 + 2);
        mma_f16(qa[1][1], a1, qh0 + 2); mma_f16(qa[1][1], a1, ql0 + 2);
        mma_f16(qa[0][2], a0, qh1);     mma_f16(qa[0][2], a0, ql1);
        mma_f16(qa[1][2], a1, qh1);     mma_f16(qa[1][2], a1, ql1);
        mma_f16(qa[0][3], a0, qh1 + 2); mma_f16(qa[0][3], a0, ql1 + 2);
        mma_f16(qa[1][3], a1, qh1 + 2); mma_f16(qa[1][3], a1, ql1 + 2);
    }
    float rp[2][2] = {};
    #pragma unroll
    for (int mt = 0; mt < 2; mt++)
        #pragma unroll
        for (int nt = 0; nt < 4; nt++) {
            const int r = wm * 32 + mt * 16 + grp;
            const int c = wn * 32 + nt * 8 + tig * 2;
            float e0 = __expf(qa[mt][nt][0]), e1 = __expf(qa[mt][nt][1]);
            float e2 = __expf(qa[mt][nt][2]), e3 = __expf(qa[mt][nt][3]);
            rp[mt][0] += e0 + e1; rp[mt][1] += e2 + e3;
            __half h0, l0, h1, l1;
            split_h(e0, h0, l0); split_h(e1, h1, l1);
            *(__half2*)&Qh[r * 72 + c] = __halves2half2(h0, h1);
            *(__half2*)&Ql[r * 72 + c] = __halves2half2(l0, l1);
            split_h(e2, h0, l0); split_h(e3, h1, l1);
            *(__half2*)&Qh[(r + 8) * 72 + c] = __halves2half2(h0, h1);
            *(__half2*)&Ql[(r + 8) * 72 + c] = __halves2half2(l0, l1);
        }
    #pragma unroll
    for (int mt = 0; mt < 2; mt++)
        #pragma unroll
        for (int p = 0; p < 2; p++) {
            float v = rp[mt][p];
            v += __shfl_xor_sync(0xffffffffu, v, 1);
            v += __shfl_xor_sync(0xffffffffu, v, 2);
            if (tig == 0) atomicAdd(&rsum[wm * 32 + mt * 16 + grp + p * 8], v);
        }
    __syncthreads();
    if (tid < 128) inv[tid] = 1.f / rsum[tid];
    __syncthreads();

    float acc[2][4][4] = {};
    #pragma unroll
    for (int ks = 0; ks < 4; ks++) {
        const unsigned kcB = (unsigned)ks * 32;
        unsigned ah0[4], ah1[4], al0[4], al1[4];
        lm4(ah0, QhU + aT0 + kcB); lm4(ah1, QhU + aT1 + kcB);
        lm4(al0, QlU + aT0 + kcB); lm4(al1, QlU + aT1 + kcB);
        unsigned bh0[4], bh1[4], bl0[4], bl1[4];
        lm4(bh0, kvhU + nb0 + kcB); lm4(bh1, kvhU + nb1 + kcB);
        lm4(bl0, kvlU + nb0 + kcB); lm4(bl1, kvlU + nb1 + kcB);
        mma_f16(acc[0][0], ah0, bh0);     mma_f16(acc[0][0], ah0, bl0);     mma_f16(acc[0][0], al0, bh0);
        mma_f16(acc[1][0], ah1, bh0);     mma_f16(acc[1][0], ah1, bl0);     mma_f16(acc[1][0], al1, bh0);
        mma_f16(acc[0][1], ah0, bh0 + 2); mma_f16(acc[0][1], ah0, bl0 + 2); mma_f16(acc[0][1], al0, bh0 + 2);
        mma_f16(acc[1][1], ah1, bh0 + 2); mma_f16(acc[1][1], ah1, bl0 + 2); mma_f16(acc[1][1], al1, bh0 + 2);
        mma_f16(acc[0][2], ah0, bh1);     mma_f16(acc[0][2], ah0, bl1);     mma_f16(acc[0][2], al0, bh1);
        mma_f16(acc[1][2], ah1, bh1);     mma_f16(acc[1][2], ah1, bl1);     mma_f16(acc[1][2], al1, bh1);
        mma_f16(acc[0][3], ah0, bh1 + 2); mma_f16(acc[0][3], ah0, bl1 + 2); mma_f16(acc[0][3], al0, bh1 + 2);
        mma_f16(acc[1][3], ah1, bh1 + 2); mma_f16(acc[1][3], ah1, bl1 + 2); mma_f16(acc[1][3], al1, bh1 + 2);
    }
    #pragma unroll
    for (int mt = 0; mt < 2; mt++)
        #pragma unroll
        for (int nt = 0; nt < 4; nt++) {
            const int r = wm * 32 + mt * 16 + grp;
            const int c = wn * 32 + nt * 8 + tig * 2;
            const float i0 = inv[r], i1 = inv[r + 8];
            __half* d0 = g_qkv + (size_t)(b * NN + n0 + r) * INNER + h * 64 + c;
            __half* d1 = g_qkv + (size_t)(b * NN + n0 + r + 8) * INNER + h * 64 + c;
            *(__half2*)d0 = __floats2half2_rn(acc[mt][nt][0] * i0, acc[mt][nt][1] * i0);
            *(__half2*)d1 = __floats2half2_rn(acc[mt][nt][2] * i1, acc[mt][nt][3] * i1);
        }
}

// ------------------------------------------------------------------------------
extern "C" void kernel_launch(void* const* d_in, const int* in_sizes, int n_in,
                              void* d_out, int out_size) {
    const float* x      = (const float*)d_in[0];
    const float* conv_w = (const float*)d_in[1];
    const float* conv_b = (const float*)d_in[2];
    const float* Wq     = (const float*)d_in[3];
    const float* Wk     = (const float*)d_in[4];
    const float* Wv     = (const float*)d_in[5];
    const float* W1     = (const float*)d_in[6];
    const float* b1     = (const float*)d_in[7];
    const float* W2     = (const float*)d_in[8];
    const float* b2     = (const float*)d_in[9];
    float* out = (float*)d_out;

    using EncFn = decltype(&cuTensorMapEncodeTiled);
    static EncFn enc = nullptr;
    if (!enc) {
        void* fp = nullptr;
        cudaDriverEntryPointQueryResult qr;
        cudaGetDriverEntryPointByVersion("cuTensorMapEncodeTiled", &fp, 12000,
                                         cudaEnableDefault, &qr);
        enc = (EncFn)fp;
    }
    static CUtensorMap mCA, mCB, mA0, mB0, mA1, mB1;
    {
        void *xp, *wp, *qkvp, *w1p, *h1p, *w2p;
        cudaGetSymbolAddress(&xp, g_xh);
        cudaGetSymbolAddress(&wp, g_wch);
        cudaGetSymbolAddress(&qkvp, g_qkv);
        cudaGetSymbolAddress(&w1p, g_w1h);
        cudaGetSymbolAddress(&h1p, g_h1);
        cudaGetSymbolAddress(&w2p, g_w2h);
        cuuint32_t e4[4] = {1, 1, 1, 1};
        cuuint64_t dA[4] = {256, 128, 128, 8};
        cuuint64_t sA[3] = {512, 65536, 8388608};
        cuuint32_t bA[4] = {64, 128, 1, 1};
        enc(&mCA, CU_TENSOR_MAP_DATA_TYPE_FLOAT16, 4, xp, dA, sA, bA, e4,
            CU_TENSOR_MAP_INTERLEAVE_NONE, CU_TENSOR_MAP_SWIZZLE_128B,
            CU_TENSOR_MAP_L2_PROMOTION_L2_128B, CU_TENSOR_MAP_FLOAT_OOB_FILL_NONE);
        cuuint64_t dB[2] = {KCONV, INNER};
        cuuint64_t sB[1] = {KCONV * 2};
        cuuint32_t bB[2] = {64, 128};
        enc(&mCB, CU_TENSOR_MAP_DATA_TYPE_FLOAT16, 2, wp, dB, sB, bB, e4,
            CU_TENSOR_MAP_INTERLEAVE_NONE, CU_TENSOR_MAP_SWIZZLE_128B,
            CU_TENSOR_MAP_L2_PROMOTION_L2_128B, CU_TENSOR_MAP_FLOAT_OOB_FILL_NONE);
        cuuint64_t dA0[2] = {512, 131072}; cuuint64_t sA0[1] = {1024};
        enc(&mA0, CU_TENSOR_MAP_DATA_TYPE_FLOAT16, 2, qkvp, dA0, sA0, bB, e4,
            CU_TENSOR_MAP_INTERLEAVE_NONE, CU_TENSOR_MAP_SWIZZLE_128B,
            CU_TENSOR_MAP_L2_PROMOTION_L2_128B, CU_TENSOR_MAP_FLOAT_OOB_FILL_NONE);
        cuuint64_t dB0[2] = {512, 256}; cuuint64_t sB0[1] = {1024};
        enc(&mB0, CU_TENSOR_MAP_DATA_TYPE_FLOAT16, 2, w1p, dB0, sB0, bB, e4,
            CU_TENSOR_MAP_INTERLEAVE_NONE, CU_TENSOR_MAP_SWIZZLE_128B,
            CU_TENSOR_MAP_L2_PROMOTION_L2_128B, CU_TENSOR_MAP_FLOAT_OOB_FILL_NONE);
        cuuint64_t dA1[2] = {256, 131072}; cuuint64_t sA1[1] = {512};
        enc(&mA1, CU_TENSOR_MAP_DATA_TYPE_FLOAT16, 2, h1p, dA1, sA1, bB, e4,
            CU_TENSOR_MAP_INTERLEAVE_NONE, CU_TENSOR_MAP_SWIZZLE_128B,
            CU_TENSOR_MAP_L2_PROMOTION_L2_128B, CU_TENSOR_MAP_FLOAT_OOB_FILL_NONE);
        cuuint64_t dB1[2] = {256, 256}; cuuint64_t sB1[1] = {512};
        enc(&mB1, CU_TENSOR_MAP_DATA_TYPE_FLOAT16, 2, w2p, dB1, sB1, bB, e4,
            CU_TENSOR_MAP_INTERLEAVE_NONE, CU_TENSOR_MAP_SWIZZLE_128B,
            CU_TENSOR_MAP_L2_PROMOTION_L2_128B, CU_TENSOR_MAP_FLOAT_OOB_FILL_NONE);
    }

    cudaFuncSetAttribute(k_conv, cudaFuncAttributeMaxDynamicSharedMemorySize, 99328);
    cudaFuncSetAttribute(k_mlp<0>, cudaFuncAttributeMaxDynamicSharedMemorySize, 99328);
    cudaFuncSetAttribute(k_mlp<1>, cudaFuncAttributeMaxDynamicSharedMemorySize, 99328);
    cudaFuncSetAttribute(k_kv,   cudaFuncAttributeMaxDynamicSharedMemorySize, 92160);
    cudaFuncSetAttribute(k_qkv,  cudaFuncAttributeMaxDynamicSharedMemorySize, 93184);

    k_wprep<<<(INNER * KCONV + 255) / 256, 256>>>(conv_w);
    k_xprep<<<((BB * NN * CC) / 4 + 255) / 256, 256>>>(x);
    k_prep2<<<(BB * HEADS * KRR * DHH) / 256, 256>>>(W1, W2, Wq, Wk, Wv);
    k_conv<<<dim3(INNER / 128, (BB * NN) / 128), 256, 99328>>>(mCA, mCB, conv_b);
    k_kv<<<dim3(8, BB * HEADS), 256, 92160>>>();
    k_kvnorm<<<(BB * HEADS * KRR * DHH) / 256, 256>>>();
    k_qkv<<<dim3(128, BB * HEADS), 256, 93184>>>();
    k_mlp<0><<<dim3(CC / 128, (BB * NN) / 128), 256, 99328>>>(mA0, mB0, b1, nullptr);
    k_mlp<1><<<dim3(CC / 128, (BB * NN) / 128), 256, 99328>>>(mA1, mB1, b2, out);
}

// round 13
// speedup vs baseline: 1.1167x; 1.1167x over previous
#include <cuda_runtime.h>
#include <cuda.h>
#include <cuda_fp16.h>
#include <math.h>

#define BB 8
#define CC 256
#define NN 16384
#define HEADS 8
#define INNER 512
#define KCONV 2304
#define KRR 64
#define DHH 64

__device__ __half g_wch[(size_t)INNER * KCONV];
__device__ __half g_xh[(size_t)BB * NN * CC];
__device__ __half g_w1h[CC * INNER];
__device__ __half g_w2h[CC * CC];
__device__ __half g_xc[(size_t)BB * NN * INNER];
__device__ float  g_colsum[BB * HEADS * KRR];
__device__ float  g_kv[BB * HEADS * KRR * DHH];
__device__ __half g_qkv[(size_t)BB * NN * INNER];
__device__ __half g_h1[(size_t)BB * NN * CC];
__device__ __half g_wqh[4096], g_wql[4096], g_wkh[4096], g_wkl[4096];
__device__ __half g_wvh[4096], g_wvl[4096];
__device__ __half g_kvth[64 * 4096], g_kvtl[64 * 4096];   // [bh][dh][kr]

__device__ __forceinline__ void mma_f16(float c[4], const unsigned a[4], const unsigned b[2]) {
    asm volatile("mma.sync.aligned.m16n8k16.row.col.f32.f16.f16.f32 "
        "{%0,%1,%2,%3}, {%4,%5,%6,%7}, {%8,%9}, {%0,%1,%2,%3};"
        : "+f"(c[0]), "+f"(c[1]), "+f"(c[2]), "+f"(c[3])
        : "r"(a[0]), "r"(a[1]), "r"(a[2]), "r"(a[3]), "r"(b[0]), "r"(b[1]));
}
__device__ __forceinline__ void lm4(unsigned r[4], unsigned a) {
    asm volatile("ldmatrix.sync.aligned.m8n8.x4.shared.b16 {%0,%1,%2,%3}, [%4];"
        : "=r"(r[0]), "=r"(r[1]), "=r"(r[2]), "=r"(r[3]) : "r"(a));
}
__device__ __forceinline__ void split_h(float f, __half& hi, __half& lo) {
    hi = __float2half_rn(f);
    lo = __float2half_rn(f - __half2float(hi));
}
__device__ __forceinline__ unsigned smem_u32(const void* p) {
    return (unsigned)__cvta_generic_to_shared(p);
}
__device__ __forceinline__ void mb_init(unsigned a, unsigned n) {
    asm volatile("mbarrier.init.shared.b64 [%0], %1;" :: "r"(a), "r"(n) : "memory");
}
__device__ __forceinline__ void mb_expect(unsigned a, unsigned bytes) {
    asm volatile("mbarrier.arrive.expect_tx.shared.b64 _, [%0], %1;"
                 :: "r"(a), "r"(bytes) : "memory");
}
__device__ __forceinline__ void mb_wait(unsigned a, unsigned ph) {
    asm volatile("{\n\t.reg .pred P;\n\tW%=:\n\t"
                 "mbarrier.try_wait.parity.shared.b64 P, [%0], %1;\n\t"
                 "@!P bra W%=;\n\t}" :: "r"(a), "r"(ph) : "memory");
}
__device__ __forceinline__ void tma4d(unsigned dst, const CUtensorMap* m,
                                      int c0, int c1, int c2, int c3, unsigned mb) {
    asm volatile("cp.async.bulk.tensor.4d.shared::cta.global.tile.mbarrier::complete_tx::bytes"
                 " [%0], [%1, {%2,%3,%4,%5}], [%6];"
                 :: "r"(dst), "l"(m), "r"(c0), "r"(c1), "r"(c2), "r"(c3), "r"(mb) : "memory");
}
__device__ __forceinline__ void tma2d(unsigned dst, const CUtensorMap* m,
                                      int c0, int c1, unsigned mb) {
    asm volatile("cp.async.bulk.tensor.2d.shared::cta.global.tile.mbarrier::complete_tx::bytes"
                 " [%0], [%1, {%2,%3}], [%4];"
                 :: "r"(dst), "l"(m), "r"(c0), "r"(c1), "r"(mb) : "memory");
}

// ---------------- prep ---------------------------------------------------------
__global__ void k_wprep(const float* __restrict__ conv_w) {
    int t = blockIdx.x * 256 + threadIdx.x;
    if (t >= INNER * KCONV) return;
    int o = t / KCONV, k = t - o * KCONV;
    g_wch[t] = __float2half_rn(conv_w[(size_t)(o * CC + (k & 255)) * 9 + (k >> 8)]);
}
__global__ void k_xprep(const float* __restrict__ x) {
    int t = blockIdx.x * 256 + threadIdx.x;
    float4 v = ((const float4*)x)[t];
    ((__half2*)g_xh)[t * 2]     = __floats2half2_rn(v.x, v.y);
    ((__half2*)g_xh)[t * 2 + 1] = __floats2half2_rn(v.z, v.w);
}
__global__ void k_prep2(const float* __restrict__ W1, const float* __restrict__ W2,
                        const float* __restrict__ Wq, const float* __restrict__ Wk,
                        const float* __restrict__ Wv) {
    int t = blockIdx.x * 256 + threadIdx.x;            // 262144
    g_kv[t] = 0.f;
    if (t < CC * INNER) g_w1h[t] = __float2half_rn(W1[t]);
    if (t < CC * CC)    g_w2h[t] = __float2half_rn(W2[t]);
    if (t < BB * HEADS * KRR) g_colsum[t] = 0.f;
    if (t < 4096) {
        split_h(Wq[t], g_wqh[t], g_wql[t]);
        split_h(Wk[t], g_wkh[t], g_wkl[t]);
        split_h(Wv[t], g_wvh[t], g_wvl[t]);
    }
}

// ---------------- conv: fp16 mma + ldmatrix, TMA 3-buffer ring, 2 CTA/SM --------
__global__ __launch_bounds__(256, 2) void k_conv(
    const __grid_constant__ CUtensorMap mA,
    const __grid_constant__ CUtensorMap mB,
    const float* __restrict__ conv_b) {
    extern __shared__ __align__(1024) char smc[];
    const unsigned sbase = smem_u32(smc);
    const int tid = threadIdx.x, lane = tid & 31, wid = tid >> 5;
    const int wm = wid & 3, wn = wid >> 2;
    const int grp = lane >> 2, tig = lane & 3;
    const int otile = blockIdx.x * 128, mtile = blockIdx.y * 128;
    const int b = mtile >> 14;
    const int py = (mtile & (NN - 1)) >> 7;

    if (tid == 0) { mb_init(sbase, 1); mb_init(sbase + 8, 1); mb_init(sbase + 16, 1); }
    __syncthreads();

    const int a_r = (lane & 7) + ((lane >> 3) & 1) * 8;
    const unsigned a_kb = (lane >> 4) * 16;
    const unsigned axor = (unsigned)(a_r & 7) << 4;
    const int b_r = (lane & 7) + (lane >> 4) * 8;
    const unsigned b_kb = ((lane >> 3) & 1) * 16;
    const unsigned bxor = (unsigned)(b_r & 7) << 4;
    const unsigned Abase0 = sbase + 1024;
    const unsigned Bbase0 = sbase + 50176;

    float acc[2][8][4] = {};

    auto issue = [&](int s) {
        const int p = s % 3;
        const int g = s >> 2;
        const int dy = g / 3 - 1, dx = g % 3 - 1;
        const int cb = (s & 3) * 64;
        mb_expect(sbase + p * 8, 32768);
        tma4d(Abase0 + p * 16384, &mA, cb, dx, py + dy, b, sbase + p * 8);
        tma2d(Bbase0 + p * 16384, &mB, g * 256 + cb, otile, sbase + p * 8);
    };

    if (tid == 0) { issue(0); issue(1); }
    for (int s = 0; s < 36; s++) {
        const int p = s % 3;
        if (s + 2 < 36 && tid == 0) issue(s + 2);
        mb_wait(sbase + p * 8, (s / 3) & 1);
        const unsigned Ab = Abase0 + p * 16384;
        const unsigned Bb = Bbase0 + p * 16384;
        #pragma unroll
        for (int ks = 0; ks < 4; ks++) {
            const unsigned ak = ((unsigned)(ks * 32) + a_kb) ^ axor;
            const unsigned bk = ((unsigned)(ks * 32) + b_kb) ^ bxor;
            unsigned a0[4], a1[4];
            lm4(a0, Ab + (unsigned)(wm * 32 + a_r) * 128 + ak);
            lm4(a1, Ab + (unsigned)(wm * 32 + 16 + a_r) * 128 + ak);
            #pragma unroll
            for (int np = 0; np < 4; np++) {
                unsigned bb[4];
                lm4(bb, Bb + (unsigned)(wn * 64 + np * 16 + b_r) * 128 + bk);
                mma_f16(acc[0][np * 2],     a0, bb);
                mma_f16(acc[1][np * 2],     a1, bb);
                mma_f16(acc[0][np * 2 + 1], a0, bb + 2);
                mma_f16(acc[1][np * 2 + 1], a1, bb + 2);
            }
        }
        __syncthreads();
    }
    #pragma unroll
    for (int mt = 0; mt < 2; mt++)
        #pragma unroll
        for (int nt = 0; nt < 8; nt++) {
            const int r = wm * 32 + mt * 16 + grp;
            const int c = wn * 64 + nt * 8 + tig * 2;
            const float b0 = conv_b[otile + c], b1 = conv_b[otile + c + 1];
            *(__half2*)(g_xc + (size_t)(mtile + r) * INNER + otile + c) =
                __floats2half2_rn(acc[mt][nt][0] + b0, acc[mt][nt][1] + b1);
            *(__half2*)(g_xc + (size_t)(mtile + r + 8) * INNER + otile + c) =
                __floats2half2_rn(acc[mt][nt][2] + b0, acc[mt][nt][3] + b1);
        }
}

// ---------------- MLP: fp16 mma + ldmatrix, TMA 3-buffer ring, 2 CTA/SM ---------
template <int MODE>
__global__ __launch_bounds__(256, 2) void k_mlp(
    const __grid_constant__ CUtensorMap mA,
    const __grid_constant__ CUtensorMap mB,
    const float* __restrict__ bias,
    float* __restrict__ out_ext) {
    constexpr int K = MODE ? CC : INNER;
    constexpr int NS = K / 64;
    extern __shared__ __align__(1024) char smc[];
    const unsigned sbase = smem_u32(smc);
    const int tid = threadIdx.x, lane = tid & 31, wid = tid >> 5;
    const int wm = wid & 3, wn = wid >> 2;
    const int grp = lane >> 2, tig = lane & 3;
    const int otile = blockIdx.x * 128, m0 = blockIdx.y * 128;

    if (tid == 0) { mb_init(sbase, 1); mb_init(sbase + 8, 1); mb_init(sbase + 16, 1); }
    __syncthreads();

    const int a_r = (lane & 7) + ((lane >> 3) & 1) * 8;
    const unsigned a_kb = (lane >> 4) * 16;
    const unsigned axor = (unsigned)(a_r & 7) << 4;
    const int b_r = (lane & 7) + (lane >> 4) * 8;
    const unsigned b_kb = ((lane >> 3) & 1) * 16;
    const unsigned bxor = (unsigned)(b_r & 7) << 4;
    const unsigned Abase0 = sbase + 1024;
    const unsigned Bbase0 = sbase + 50176;

    float acc[2][8][4] = {};

    auto issue = [&](int s) {
        const int p = s % 3;
        mb_expect(sbase + p * 8, 32768);
        tma2d(Abase0 + p * 16384, &mA, s * 64, m0, sbase + p * 8);
        tma2d(Bbase0 + p * 16384, &mB, s * 64, otile, sbase + p * 8);
    };

    if (tid == 0) { issue(0); if (NS > 1) issue(1); }
    for (int s = 0; s < NS; s++) {
        const int p = s % 3;
        if (s + 2 < NS && tid == 0) issue(s + 2);
        mb_wait(sbase + p * 8, (s / 3) & 1);
        const unsigned Ab = Abase0 + p * 16384;
        const unsigned Bb = Bbase0 + p * 16384;
        #pragma unroll
        for (int ks = 0; ks < 4; ks++) {
            const unsigned ak = ((unsigned)(ks * 32) + a_kb) ^ axor;
            const unsigned bk = ((unsigned)(ks * 32) + b_kb) ^ bxor;
            unsigned a0[4], a1[4];
            lm4(a0, Ab + (unsigned)(wm * 32 + a_r) * 128 + ak);
            lm4(a1, Ab + (unsigned)(wm * 32 + 16 + a_r) * 128 + ak);
            #pragma unroll
            for (int np = 0; np < 4; np++) {
                unsigned bb[4];
                lm4(bb, Bb + (unsigned)(wn * 64 + np * 16 + b_r) * 128 + bk);
                mma_f16(acc[0][np * 2],     a0, bb);
                mma_f16(acc[1][np * 2],     a1, bb);
                mma_f16(acc[0][np * 2 + 1], a0, bb + 2);
                mma_f16(acc[1][np * 2 + 1], a1, bb + 2);
            }
        }
        __syncthreads();
    }
    #pragma unroll
    for (int mt = 0; mt < 2; mt++)
        #pragma unroll
        for (int nt = 0; nt < 8; nt++) {
            const int r = wm * 32 + mt * 16 + grp;
            const int c = wn * 64 + nt * 8 + tig * 2;
            const float b0 = bias[otile + c], b1 = bias[otile + c + 1];
            float v[4] = {acc[mt][nt][0] + b0, acc[mt][nt][1] + b1,
                          acc[mt][nt][2] + b0, acc[mt][nt][3] + b1};
            if (MODE == 0) {
                #pragma unroll
                for (int j = 0; j < 4; j++)
                    v[j] = 0.5f * v[j] * (1.0f + erff(v[j] * 0.70710678118654752f));
                *(__half2*)(g_h1 + (size_t)(m0 + r) * CC + otile + c) =
                    __floats2half2_rn(v[0], v[1]);
                *(__half2*)(g_h1 + (size_t)(m0 + r + 8) * CC + otile + c) =
                    __floats2half2_rn(v[2], v[3]);
            } else {
                *(float2*)(out_ext + (size_t)(m0 + r) * CC + otile + c) =
                    make_float2(v[0], v[1]);
                *(float2*)(out_ext + (size_t)(m0 + r + 8) * CC + otile + c) =
                    make_float2(v[2], v[3]);
            }
        }
}

// ---------------- k_kv: fp16 split mma, ldmatrix, double-buffered X ------------
__global__ __launch_bounds__(256) void k_kv() {
    extern __shared__ __half sh[];
    __half *Xs0 = sh, *Xs1 = sh + 4608;
    __half *Wkh = sh + 9216,  *Wkl = sh + 13824;
    __half *Wvh = sh + 18432, *Wvl = sh + 23040;
    __half *Kth = sh + 27648, *Ktl = sh + 32256;
    __half *Vth = sh + 36864, *Vtl = sh + 41472;

    const int tid = threadIdx.x, lane = tid & 31, wid = tid >> 5;
    const int wm = wid & 3, wn = wid >> 2;
    const int grp = lane >> 2, tig = lane & 3;
    const int bh = blockIdx.y, b = bh >> 3, h = bh & 7;
    const int r = tid >> 2, c0 = (tid & 3) * 16;

    {
        const int gsrc = r * 64 + c0;
        const int sdst = r * 72 + c0;
        *(uint4*)&Wkh[sdst]     = *(const uint4*)&g_wkh[gsrc];
        *(uint4*)&Wkh[sdst + 8] = *(const uint4*)&g_wkh[gsrc + 8];
        *(uint4*)&Wkl[sdst]     = *(const uint4*)&g_wkl[gsrc];
        *(uint4*)&Wkl[sdst + 8] = *(const uint4*)&g_wkl[gsrc + 8];
        *(uint4*)&Wvh[sdst]     = *(const uint4*)&g_wvh[gsrc];
        *(uint4*)&Wvh[sdst + 8] = *(const uint4*)&g_wvh[gsrc + 8];
        *(uint4*)&Wvl[sdst]     = *(const uint4*)&g_wvl[gsrc];
        *(uint4*)&Wvl[sdst + 8] = *(const uint4*)&g_wvl[gsrc + 8];
    }

    const int la_r = (lane & 7) + ((lane >> 3) & 1) * 8;
    const unsigned a_off = (unsigned)la_r * 144 + (lane >> 4) * 16;
    const int lb_r = (lane & 7) + (lane >> 4) * 8;
    const unsigned b_off = (unsigned)lb_r * 144 + ((lane >> 3) & 1) * 16;
    const unsigned Xs0U = smem_u32(Xs0);
    const unsigned WkhU = smem_u32(Wkh), WklU = smem_u32(Wkl);
    const unsigned WvhU = smem_u32(Wvh), WvlU = smem_u32(Wvl);
    const unsigned KthU = smem_u32(Kth), KtlU = smem_u32(Ktl);
    const unsigned VthU = smem_u32(Vth), VtlU = smem_u32(Vtl);
    const unsigned aTile = (unsigned)(wm * 16) * 144 + a_off;
    const unsigned nb0 = (unsigned)(wn * 32) * 144 + b_off;
    const unsigned nb1 = nb0 + 16u * 144;

    float kvacc[4][4] = {};
    float csum[8] = {};
    const int mrow = wm * 16 + grp;

    for (int ch = 0; ch < 32; ch++) {
        const int n0 = blockIdx.x * 2048 + ch * 64;
        __half* Xc = (ch & 1) ? Xs1 : Xs0;
        {
            const __half* xsrc = g_xc + (size_t)(b * NN + n0 + r) * INNER + h * 64 + c0;
            *(uint4*)&Xc[r * 72 + c0]     = *(const uint4*)xsrc;
            *(uint4*)&Xc[r * 72 + c0 + 8] = *(const uint4*)(xsrc + 8);
        }
        __syncthreads();

        const unsigned XcU = Xs0U + (unsigned)(ch & 1) * 9216;
        float ka[4][4] = {}, va[4][4] = {};
        #pragma unroll
        for (int ks = 0; ks < 4; ks++) {
            const unsigned kcB = (unsigned)ks * 32;
            unsigned a[4];
            lm4(a, XcU + aTile + kcB);
            unsigned kh0[4], kh1[4], kl0[4], kl1[4];
            unsigned vh0[4], vh1[4], vl0[4], vl1[4];
            lm4(kh0, WkhU + nb0 + kcB); lm4(kh1, WkhU + nb1 + kcB);
            lm4(kl0, WklU + nb0 + kcB); lm4(kl1, WklU + nb1 + kcB);
            lm4(vh0, WvhU + nb0 + kcB); lm4(vh1, WvhU + nb1 + kcB);
            lm4(vl0, WvlU + nb0 + kcB); lm4(vl1, WvlU + nb1 + kcB);
            mma_f16(ka[0], a, kh0);     mma_f16(ka[0], a, kl0);
            mma_f16(ka[1], a, kh0 + 2); mma_f16(ka[1], a, kl0 + 2);
            mma_f16(ka[2], a, kh1);     mma_f16(ka[2], a, kl1);
            mma_f16(ka[3], a, kh1 + 2); mma_f16(ka[3], a, kl1 + 2);
            mma_f16(va[0], a, vh0);     mma_f16(va[0], a, vl0);
            mma_f16(va[1], a, vh0 + 2); mma_f16(va[1], a, vl0 + 2);
            mma_f16(va[2], a, vh1);     mma_f16(va[2], a, vl1);
            mma_f16(va[3], a, vh1 + 2); mma_f16(va[3], a, vl1 + 2);
        }
        #pragma unroll
        for (int nt = 0; nt < 4; nt++) {
            const int c = wn * 32 + nt * 8 + tig * 2;
            float e;
            e = __expf(ka[nt][0]); csum[nt*2]   += e; split_h(e, Kth[c*72+mrow],       Ktl[c*72+mrow]);
            e = __expf(ka[nt][1]); csum[nt*2+1] += e; split_h(e, Kth[(c+1)*72+mrow],   Ktl[(c+1)*72+mrow]);
            e = __expf(ka[nt][2]); csum[nt*2]   += e; split_h(e, Kth[c*72+mrow+8],     Ktl[c*72+mrow+8]);
            e = __expf(ka[nt][3]); csum[nt*2+1] += e; split_h(e, Kth[(c+1)*72+mrow+8], Ktl[(c+1)*72+mrow+8]);
            split_h(va[nt][0], Vth[c*72+mrow],       Vtl[c*72+mrow]);
            split_h(va[nt][1], Vth[(c+1)*72+mrow],   Vtl[(c+1)*72+mrow]);
            split_h(va[nt][2], Vth[c*72+mrow+8],     Vtl[c*72+mrow+8]);
            split_h(va[nt][3], Vth[(c+1)*72+mrow+8], Vtl[(c+1)*72+mrow+8]);
        }
        __syncthreads();

        #pragma unroll
        for (int ks = 0; ks < 4; ks++) {
            const unsigned kcB = (unsigned)ks * 32;
            unsigned ah[4], al[4];
            lm4(ah, KthU + aTile + kcB);
            lm4(al, KtlU + aTile + kcB);
            unsigned bh0[4], bh1[4], bl0[4], bl1[4];
            lm4(bh0, VthU + nb0 + kcB); lm4(bh1, VthU + nb1 + kcB);
            lm4(bl0, VtlU + nb0 + kcB); lm4(bl1, VtlU + nb1 + kcB);
            mma_f16(kvacc[0], ah, bh0);     mma_f16(kvacc[0], ah, bl0);     mma_f16(kvacc[0], al, bh0);
            mma_f16(kvacc[1], ah, bh0 + 2); mma_f16(kvacc[1], ah, bl0 + 2); mma_f16(kvacc[1], al, bh0 + 2);
            mma_f16(kvacc[2], ah, bh1);     mma_f16(kvacc[2], ah, bl1);     mma_f16(kvacc[2], al, bh1);
            mma_f16(kvacc[3], ah, bh1 + 2); mma_f16(kvacc[3], ah, bl1 + 2); mma_f16(kvacc[3], al, bh1 + 2);
        }
    }

    float* kvbase = g_kv + (size_t)bh * (KRR * DHH);
    #pragma unroll
    for (int nt = 0; nt < 4; nt++) {
        const int c = wn * 32 + nt * 8 + tig * 2;
        atomicAdd(kvbase + mrow * 64 + c,           kvacc[nt][0]);
        atomicAdd(kvbase + mrow * 64 + c + 1,       kvacc[nt][1]);
        atomicAdd(kvbase + (mrow + 8) * 64 + c,     kvacc[nt][2]);
        atomicAdd(kvbase + (mrow + 8) * 64 + c + 1, kvacc[nt][3]);
    }
    #pragma unroll
    for (int idx = 0; idx < 8; idx++) {
        const int c = wn * 32 + (idx >> 1) * 8 + tig * 2 + (idx & 1);
        atomicAdd(g_colsum + bh * 64 + c, csum[idx]);
    }
}

// ---------------- kv normalize + transpose + split ------------------------------
__global__ void k_kvnorm() {
    int i = blockIdx.x * 256 + threadIdx.x;
    float v = g_kv[i] / g_colsum[i >> 6];
    int bh = i >> 12, kr = (i >> 6) & 63, dh = i & 63;
    __half hi, lo;
    split_h(v, hi, lo);
    int o = bh * 4096 + dh * 64 + kr;
    g_kvth[o] = hi;
    g_kvtl[o] = lo;
}

// ---------------- k_qkv: fp16 split mma, ldmatrix fragments ---------------------
__global__ __launch_bounds__(256) void k_qkv() {
    extern __shared__ __half sh[];
    __half *Xs   = sh;
    __half *Qh   = sh + 9216,  *Ql  = sh + 18432;
    __half *Wqh  = sh + 27648, *Wql = sh + 32256;
    __half *kvth = sh + 36864, *kvtl = sh + 41472;
    float  *rsum = (float*)(sh + 46080);
    float  *inv  = rsum + 128;

    const int tid = threadIdx.x, lane = tid & 31, wid = tid >> 5;
    const int wm = wid & 3, wn = wid >> 2;
    const int grp = lane >> 2, tig = lane & 3;
    const int bh = blockIdx.y, b = bh >> 3, h = bh & 7;
    const int n0 = blockIdx.x * 128;

    if (tid < 128) rsum[tid] = 0.f;
    {
        const int r = tid >> 2, c0 = (tid & 3) * 16;
        const int gsrc = r * 64 + c0;
        const int sdst = r * 72 + c0;
        *(uint4*)&Wqh[sdst]     = *(const uint4*)&g_wqh[gsrc];
        *(uint4*)&Wqh[sdst + 8] = *(const uint4*)&g_wqh[gsrc + 8];
        *(uint4*)&Wql[sdst]     = *(const uint4*)&g_wql[gsrc];
        *(uint4*)&Wql[sdst + 8] = *(const uint4*)&g_wql[gsrc + 8];
        const __half* kvh = g_kvth + bh * 4096 + gsrc;
        const __half* kvl = g_kvtl + bh * 4096 + gsrc;
        *(uint4*)&kvth[sdst]     = *(const uint4*)kvh;
        *(uint4*)&kvth[sdst + 8] = *(const uint4*)(kvh + 8);
        *(uint4*)&kvtl[sdst]     = *(const uint4*)kvl;
        *(uint4*)&kvtl[sdst + 8] = *(const uint4*)(kvl + 8);
    }
    {
        const int xr = tid >> 1, xc0 = (tid & 1) * 32;
        const __half* xsrc = g_xc + (size_t)(b * NN + n0 + xr) * INNER + h * 64 + xc0;
        #pragma unroll
        for (int j = 0; j < 4; j++)
            *(uint4*)&Xs[xr * 72 + xc0 + j * 8] = *(const uint4*)(xsrc + j * 8);
    }
    __syncthreads();

    const int la_r = (lane & 7) + ((lane >> 3) & 1) * 8;
    const unsigned a_off = (unsigned)la_r * 144 + (lane >> 4) * 16;
    const int lb_r = (lane & 7) + (lane >> 4) * 8;
    const unsigned b_off = (unsigned)lb_r * 144 + ((lane >> 3) & 1) * 16;
    const unsigned XsU = smem_u32(Xs), QhU = smem_u32(Qh), QlU = smem_u32(Ql);
    const unsigned WqhU = smem_u32(Wqh), WqlU = smem_u32(Wql);
    const unsigned kvhU = smem_u32(kvth), kvlU = smem_u32(kvtl);
    const unsigned aT0 = (unsigned)(wm * 32) * 144 + a_off;
    const unsigned aT1 = aT0 + 16u * 144;
    const unsigned nb0 = (unsigned)(wn * 32) * 144 + b_off;
    const unsigned nb1 = nb0 + 16u * 144;

    float qa[2][4][4] = {};
    #pragma unroll
    for (int ks = 0; ks < 4; ks++) {
        const unsigned kcB = (unsigned)ks * 32;
        unsigned a0[4], a1[4];
        lm4(a0, XsU + aT0 + kcB);
        lm4(a1, XsU + aT1 + kcB);
        unsigned qh0[4], qh1[4], ql0[4], ql1[4];
        lm4(qh0, WqhU + nb0 + kcB); lm4(qh1, WqhU + nb1 + kcB);
        lm4(ql0, WqlU + nb0 + kcB); lm4(ql1, WqlU + nb1 + kcB);
        mma_f16(qa[0][0], a0, qh0);     mma_f16(qa[0][0], a0, ql0);
        mma_f16(qa[1][0], a1, qh0);     mma_f16(qa[1][0], a1, ql0);
        mma_f16(qa[0][1], a0, qh0 + 2); mma_f16(qa[0][1], a0, ql0 + 2);
        mma_f16(qa[1][1], a1, qh0 + 2); mma_f16(qa[1][1], a1, ql0 + 2);
        mma_f16(qa[0][2], a0, qh1);     mma_f16(qa[0][2], a0, ql1);
        mma_f16(qa[1][2], a1, qh1);     mma_f16(qa[1][2], a1, ql1);
        mma_f16(qa[0][3], a0, qh1 + 2); mma_f16(qa[0][3], a0, ql1 + 2);
        mma_f16(qa[1][3], a1, qh1 + 2); mma_f16(qa[1][3], a1, ql1 + 2);
    }
    float rp[2][2] = {};
    #pragma unroll
    for (int mt = 0; mt < 2; mt++)
        #pragma unroll
        for (int nt = 0; nt < 4; nt++) {
            const int r = wm * 32 + mt * 16 + grp;
            const int c = wn * 32 + nt * 8 + tig * 2;
            float e0 = __expf(qa[mt][nt][0]), e1 = __expf(qa[mt][nt][1]);
            float e2 = __expf(qa[mt][nt][2]), e3 = __expf(qa[mt][nt][3]);
            rp[mt][0] += e0 + e1; rp[mt][1] += e2 + e3;
            __half h0, l0, h1, l1;
            split_h(e0, h0, l0); split_h(e1, h1, l1);
            *(__half2*)&Qh[r * 72 + c] = __halves2half2(h0, h1);
            *(__half2*)&Ql[r * 72 + c] = __halves2half2(l0, l1);
            split_h(e2, h0, l0); split_h(e3, h1, l1);
            *(__half2*)&Qh[(r + 8) * 72 + c] = __halves2half2(h0, h1);
            *(__half2*)&Ql[(r + 8) * 72 + c] = __halves2half2(l0, l1);
        }
    #pragma unroll
    for (int mt = 0; mt < 2; mt++)
        #pragma unroll
        for (int p = 0; p < 2; p++) {
            float v = rp[mt][p];
            v += __shfl_xor_sync(0xffffffffu, v, 1);
            v += __shfl_xor_sync(0xffffffffu, v, 2);
            if (tig == 0) atomicAdd(&rsum[wm * 32 + mt * 16 + grp + p * 8], v);
        }
    __syncthreads();
    if (tid < 128) inv[tid] = 1.f / rsum[tid];
    __syncthreads();

    float acc[2][4][4] = {};
    #pragma unroll
    for (int ks = 0; ks < 4; ks++) {
        const unsigned kcB = (unsigned)ks * 32;
        unsigned ah0[4], ah1[4], al0[4], al1[4];
        lm4(ah0, QhU + aT0 + kcB); lm4(ah1, QhU + aT1 + kcB);
        lm4(al0, QlU + aT0 + kcB); lm4(al1, QlU + aT1 + kcB);
        unsigned bh0[4], bh1[4], bl0[4], bl1[4];
        lm4(bh0, kvhU + nb0 + kcB); lm4(bh1, kvhU + nb1 + kcB);
        lm4(bl0, kvlU + nb0 + kcB); lm4(bl1, kvlU + nb1 + kcB);
        mma_f16(acc[0][0], ah0, bh0);     mma_f16(acc[0][0], ah0, bl0);     mma_f16(acc[0][0], al0, bh0);
        mma_f16(acc[1][0], ah1, bh0);     mma_f16(acc[1][0], ah1, bl0);     mma_f16(acc[1][0], al1, bh0);
        mma_f16(acc[0][1], ah0, bh0 + 2); mma_f16(acc[0][1], ah0, bl0 + 2); mma_f16(acc[0][1], al0, bh0 + 2);
        mma_f16(acc[1][1], ah1, bh0 + 2); mma_f16(acc[1][1], ah1, bl0 + 2); mma_f16(acc[1][1], al1, bh0 + 2);
        mma_f16(acc[0][2], ah0, bh1);     mma_f16(acc[0][2], ah0, bl1);     mma_f16(acc[0][2], al0, bh1);
        mma_f16(acc[1][2], ah1, bh1);     mma_f16(acc[1][2], ah1, bl1);     mma_f16(acc[1][2], al1, bh1);
        mma_f16(acc[0][3], ah0, bh1 + 2); mma_f16(acc[0][3], ah0, bl1 + 2); mma_f16(acc[0][3], al0, bh1 + 2);
        mma_f16(acc[1][3], ah1, bh1 + 2); mma_f16(acc[1][3], ah1, bl1 + 2); mma_f16(acc[1][3], al1, bh1 + 2);
    }
    #pragma unroll
    for (int mt = 0; mt < 2; mt++)
        #pragma unroll
        for (int nt = 0; nt < 4; nt++) {
            const int r = wm * 32 + mt * 16 + grp;
            const int c = wn * 32 + nt * 8 + tig * 2;
            const float i0 = inv[r], i1 = inv[r + 8];
            __half* d0 = g_qkv + (size_t)(b * NN + n0 + r) * INNER + h * 64 + c;
            __half* d1 = g_qkv + (size_t)(b * NN + n0 + r + 8) * INNER + h * 64 + c;
            *(__half2*)d0 = __floats2half2_rn(acc[mt][nt][0] * i0, acc[mt][nt][1] * i0);
            *(__half2*)d1 = __floats2half2_rn(acc[mt][nt][2] * i1, acc[mt][nt][3] * i1);
        }
}

// ------------------------------------------------------------------------------
extern "C" void kernel_launch(void* const* d_in, const int* in_sizes, int n_in,
                              void* d_out, int out_size) {
    const float* x      = (const float*)d_in[0];
    const float* conv_w = (const float*)d_in[1];
    const float* conv_b = (const float*)d_in[2];
    const float* Wq     = (const float*)d_in[3];
    const float* Wk     = (const float*)d_in[4];
    const float* Wv     = (const float*)d_in[5];
    const float* W1     = (const float*)d_in[6];
    const float* b1     = (const float*)d_in[7];
    const float* W2     = (const float*)d_in[8];
    const float* b2     = (const float*)d_in[9];
    float* out = (float*)d_out;

    using EncFn = decltype(&cuTensorMapEncodeTiled);
    static EncFn enc = nullptr;
    if (!enc) {
        void* fp = nullptr;
        cudaDriverEntryPointQueryResult qr;
        cudaGetDriverEntryPointByVersion("cuTensorMapEncodeTiled", &fp, 12000,
                                         cudaEnableDefault, &qr);
        enc = (EncFn)fp;
    }
    static CUtensorMap mCA, mCB, mA0, mB0, mA1, mB1;
    {
        void *xp, *wp, *qkvp, *w1p, *h1p, *w2p;
        cudaGetSymbolAddress(&xp, g_xh);
        cudaGetSymbolAddress(&wp, g_wch);
        cudaGetSymbolAddress(&qkvp, g_qkv);
        cudaGetSymbolAddress(&w1p, g_w1h);
        cudaGetSymbolAddress(&h1p, g_h1);
        cudaGetSymbolAddress(&w2p, g_w2h);
        cuuint32_t e4[4] = {1, 1, 1, 1};
        cuuint64_t dA[4] = {256, 128, 128, 8};
        cuuint64_t sA[3] = {512, 65536, 8388608};
        cuuint32_t bA[4] = {64, 128, 1, 1};
        enc(&mCA, CU_TENSOR_MAP_DATA_TYPE_FLOAT16, 4, xp, dA, sA, bA, e4,
            CU_TENSOR_MAP_INTERLEAVE_NONE, CU_TENSOR_MAP_SWIZZLE_128B,
            CU_TENSOR_MAP_L2_PROMOTION_L2_128B, CU_TENSOR_MAP_FLOAT_OOB_FILL_NONE);
        cuuint64_t dB[2] = {KCONV, INNER};
        cuuint64_t sB[1] = {KCONV * 2};
        cuuint32_t bB[2] = {64, 128};
        enc(&mCB, CU_TENSOR_MAP_DATA_TYPE_FLOAT16, 2, wp, dB, sB, bB, e4,
            CU_TENSOR_MAP_INTERLEAVE_NONE, CU_TENSOR_MAP_SWIZZLE_128B,
            CU_TENSOR_MAP_L2_PROMOTION_L2_128B, CU_TENSOR_MAP_FLOAT_OOB_FILL_NONE);
        cuuint64_t dA0[2] = {512, 131072}; cuuint64_t sA0[1] = {1024};
        enc(&mA0, CU_TENSOR_MAP_DATA_TYPE_FLOAT16, 2, qkvp, dA0, sA0, bB, e4,
            CU_TENSOR_MAP_INTERLEAVE_NONE, CU_TENSOR_MAP_SWIZZLE_128B,
            CU_TENSOR_MAP_L2_PROMOTION_L2_128B, CU_TENSOR_MAP_FLOAT_OOB_FILL_NONE);
        cuuint64_t dB0[2] = {512, 256}; cuuint64_t sB0[1] = {1024};
        enc(&mB0, CU_TENSOR_MAP_DATA_TYPE_FLOAT16, 2, w1p, dB0, sB0, bB, e4,
            CU_TENSOR_MAP_INTERLEAVE_NONE, CU_TENSOR_MAP_SWIZZLE_128B,
            CU_TENSOR_MAP_L2_PROMOTION_L2_128B, CU_TENSOR_MAP_FLOAT_OOB_FILL_NONE);
        cuuint64_t dA1[2] = {256, 131072}; cuuint64_t sA1[1] = {512};
        enc(&mA1, CU_TENSOR_MAP_DATA_TYPE_FLOAT16, 2, h1p, dA1, sA1, bB, e4,
            CU_TENSOR_MAP_INTERLEAVE_NONE, CU_TENSOR_MAP_SWIZZLE_128B,
            CU_TENSOR_MAP_L2_PROMOTION_L2_128B, CU_TENSOR_MAP_FLOAT_OOB_FILL_NONE);
        cuuint64_t dB1[2] = {256, 256}; cuuint64_t sB1[1] = {512};
        enc(&mB1, CU_TENSOR_MAP_DATA_TYPE_FLOAT16, 2, w2p, dB1, sB1, bB, e4,
            CU_TENSOR_MAP_INTERLEAVE_NONE, CU_TENSOR_MAP_SWIZZLE_128B,
            CU_TENSOR_MAP_L2_PROMOTION_L2_128B, CU_TENSOR_MAP_FLOAT_OOB_FILL_NONE);
    }

    cudaFuncSetAttribute(k_conv, cudaFuncAttributeMaxDynamicSharedMemorySize, 99328);
    cudaFuncSetAttribute(k_mlp<0>, cudaFuncAttributeMaxDynamicSharedMemorySize, 99328);
    cudaFuncSetAttribute(k_mlp<1>, cudaFuncAttributeMaxDynamicSharedMemorySize, 99328);
    cudaFuncSetAttribute(k_kv,   cudaFuncAttributeMaxDynamicSharedMemorySize, 92160);
    cudaFuncSetAttribute(k_qkv,  cudaFuncAttributeMaxDynamicSharedMemorySize, 93184);

    k_wprep<<<(INNER * KCONV + 255) / 256, 256>>>(conv_w);
    k_xprep<<<((BB * NN * CC) / 4 + 255) / 256, 256>>>(x);
    k_prep2<<<(BB * HEADS * KRR * DHH) / 256, 256>>>(W1, W2, Wq, Wk, Wv);
    k_conv<<<dim3(INNER / 128, (BB * NN) / 128), 256, 99328>>>(mCA, mCB, conv_b);
    k_kv<<<dim3(8, BB * HEADS), 256, 92160>>>();
    k_kvnorm<<<(BB * HEADS * KRR * DHH) / 256, 256>>>();
    k_qkv<<<dim3(128, BB * HEADS), 256, 93184>>>();
    k_mlp<0><<<dim3(CC / 128, (BB * NN) / 128), 256, 99328>>>(mA0, mB0, b1, nullptr);
    k_mlp<1><<<dim3(CC / 128, (BB * NN) / 128), 256, 99328>>>(mA1, mB1, b2, out);
}

// round 15
// speedup vs baseline: 1.1319x; 1.0136x over previous
#include <cuda_runtime.h>
#include <cuda.h>
#include <cuda_fp16.h>
#include <math.h>

#define BB 8
#define CC 256
#define NN 16384
#define HEADS 8
#define INNER 512
#define KCONV 2304
#define KRR 64
#define DHH 64

__device__ __half g_wch[(size_t)INNER * KCONV];
__device__ __half g_xh[(size_t)BB * NN * CC];
__device__ __half g_w1h[CC * INNER];
__device__ __half g_w2h[CC * CC];
__device__ __half g_xc[(size_t)BB * NN * INNER];
__device__ float  g_colsum[BB * HEADS * KRR];
__device__ float  g_kv[BB * HEADS * KRR * DHH];
__device__ __half g_qkv[(size_t)BB * NN * INNER];
__device__ __half g_h1[(size_t)BB * NN * CC];
__device__ __half g_wqh[4096], g_wql[4096], g_wkh[4096], g_wkl[4096];
__device__ __half g_wvh[4096], g_wvl[4096];
__device__ __half g_kvth[64 * 4096], g_kvtl[64 * 4096];   // [bh][dh][kr]

__device__ __forceinline__ void mma_f16(float c[4], const unsigned a[4], const unsigned b[2]) {
    asm volatile("mma.sync.aligned.m16n8k16.row.col.f32.f16.f16.f32 "
        "{%0,%1,%2,%3}, {%4,%5,%6,%7}, {%8,%9}, {%0,%1,%2,%3};"
        : "+f"(c[0]), "+f"(c[1]), "+f"(c[2]), "+f"(c[3])
        : "r"(a[0]), "r"(a[1]), "r"(a[2]), "r"(a[3]), "r"(b[0]), "r"(b[1]));
}
__device__ __forceinline__ void lm4(unsigned r[4], unsigned a) {
    asm volatile("ldmatrix.sync.aligned.m8n8.x4.shared.b16 {%0,%1,%2,%3}, [%4];"
        : "=r"(r[0]), "=r"(r[1]), "=r"(r[2]), "=r"(r[3]) : "r"(a));
}
__device__ __forceinline__ void split_h(float f, __half& hi, __half& lo) {
    hi = __float2half_rn(f);
    lo = __float2half_rn(f - __half2float(hi));
}
__device__ __forceinline__ unsigned smem_u32(const void* p) {
    return (unsigned)__cvta_generic_to_shared(p);
}
__device__ __forceinline__ void mb_init(unsigned a, unsigned n) {
    asm volatile("mbarrier.init.shared.b64 [%0], %1;" :: "r"(a), "r"(n) : "memory");
}
__device__ __forceinline__ void mb_expect(unsigned a, unsigned bytes) {
    asm volatile("mbarrier.arrive.expect_tx.shared.b64 _, [%0], %1;"
                 :: "r"(a), "r"(bytes) : "memory");
}
__device__ __forceinline__ void mb_wait(unsigned a, unsigned ph) {
    asm volatile("{\n\t.reg .pred P;\n\tW%=:\n\t"
                 "mbarrier.try_wait.parity.shared.b64 P, [%0], %1;\n\t"
                 "@!P bra W%=;\n\t}" :: "r"(a), "r"(ph) : "memory");
}
__device__ __forceinline__ void tma4d(unsigned dst, const CUtensorMap* m,
                                      int c0, int c1, int c2, int c3, unsigned mb) {
    asm volatile("cp.async.bulk.tensor.4d.shared::cta.global.tile.mbarrier::complete_tx::bytes"
                 " [%0], [%1, {%2,%3,%4,%5}], [%6];"
                 :: "r"(dst), "l"(m), "r"(c0), "r"(c1), "r"(c2), "r"(c3), "r"(mb) : "memory");
}
__device__ __forceinline__ void tma2d(unsigned dst, const CUtensorMap* m,
                                      int c0, int c1, unsigned mb) {
    asm volatile("cp.async.bulk.tensor.2d.shared::cta.global.tile.mbarrier::complete_tx::bytes"
                 " [%0], [%1, {%2,%3}], [%4];"
                 :: "r"(dst), "l"(m), "r"(c0), "r"(c1), "r"(mb) : "memory");
}

// ---------------- fused prep (grid covers ALL of x: 8388608 float4s) ------------
__global__ void k_prep(const float* __restrict__ x, const float* __restrict__ conv_w,
                       const float* __restrict__ W1, const float* __restrict__ W2,
                       const float* __restrict__ Wq, const float* __restrict__ Wk,
                       const float* __restrict__ Wv) {
    int t = blockIdx.x * 256 + threadIdx.x;            // 0 .. 8388607
    float4 v = ((const float4*)x)[t];
    ((__half2*)g_xh)[t * 2]     = __floats2half2_rn(v.x, v.y);
    ((__half2*)g_xh)[t * 2 + 1] = __floats2half2_rn(v.z, v.w);
    if (t < INNER * KCONV) {
        int o = t / KCONV, k = t - o * KCONV;
        g_wch[t] = __float2half_rn(conv_w[(size_t)(o * CC + (k & 255)) * 9 + (k >> 8)]);
    }
    if (t < BB * HEADS * KRR * DHH) g_kv[t] = 0.f;
    if (t < CC * INNER) g_w1h[t] = __float2half_rn(W1[t]);
    if (t < CC * CC)    g_w2h[t] = __float2half_rn(W2[t]);
    if (t < BB * HEADS * KRR) g_colsum[t] = 0.f;
    if (t < 4096) {
        split_h(Wq[t], g_wqh[t], g_wql[t]);
        split_h(Wk[t], g_wkh[t], g_wkl[t]);
        split_h(Wv[t], g_wvh[t], g_wvl[t]);
    }
}

// ---------------- conv: fp16 mma + ldmatrix, TMA 3-buffer ring, 2 CTA/SM --------
__global__ __launch_bounds__(256, 2) void k_conv(
    const __grid_constant__ CUtensorMap mA,
    const __grid_constant__ CUtensorMap mB,
    const float* __restrict__ conv_b) {
    extern __shared__ __align__(1024) char smc[];
    const unsigned sbase = smem_u32(smc);
    const int tid = threadIdx.x, lane = tid & 31, wid = tid >> 5;
    const int wm = wid & 3, wn = wid >> 2;
    const int grp = lane >> 2, tig = lane & 3;
    const int otile = blockIdx.x * 128, mtile = blockIdx.y * 128;
    const int b = mtile >> 14;
    const int py = (mtile & (NN - 1)) >> 7;

    if (tid == 0) { mb_init(sbase, 1); mb_init(sbase + 8, 1); mb_init(sbase + 16, 1); }
    __syncthreads();

    const int a_r = (lane & 7) + ((lane >> 3) & 1) * 8;
    const unsigned a_kb = (lane >> 4) * 16;
    const unsigned axor = (unsigned)(a_r & 7) << 4;
    const int b_r = (lane & 7) + (lane >> 4) * 8;
    const unsigned b_kb = ((lane >> 3) & 1) * 16;
    const unsigned bxor = (unsigned)(b_r & 7) << 4;
    const unsigned Abase0 = sbase + 1024;
    const unsigned Bbase0 = sbase + 50176;

    float acc[2][8][4] = {};

    auto issue = [&](int s) {
        const int p = s % 3;
        const int g = s >> 2;
        const int dy = g / 3 - 1, dx = g % 3 - 1;
        const int cb = (s & 3) * 64;
        mb_expect(sbase + p * 8, 32768);
        tma4d(Abase0 + p * 16384, &mA, cb, dx, py + dy, b, sbase + p * 8);
        tma2d(Bbase0 + p * 16384, &mB, g * 256 + cb, otile, sbase + p * 8);
    };

    if (tid == 0) { issue(0); issue(1); }
    for (int s = 0; s < 36; s++) {
        const int p = s % 3;
        if (s + 2 < 36 && tid == 0) issue(s + 2);
        mb_wait(sbase + p * 8, (s / 3) & 1);
        const unsigned Ab = Abase0 + p * 16384;
        const unsigned Bb = Bbase0 + p * 16384;
        #pragma unroll
        for (int ks = 0; ks < 4; ks++) {
            const unsigned ak = ((unsigned)(ks * 32) + a_kb) ^ axor;
            const unsigned bk = ((unsigned)(ks * 32) + b_kb) ^ bxor;
            unsigned a0[4], a1[4];
            lm4(a0, Ab + (unsigned)(wm * 32 + a_r) * 128 + ak);
            lm4(a1, Ab + (unsigned)(wm * 32 + 16 + a_r) * 128 + ak);
            #pragma unroll
            for (int np = 0; np < 4; np++) {
                unsigned bb[4];
                lm4(bb, Bb + (unsigned)(wn * 64 + np * 16 + b_r) * 128 + bk);
                mma_f16(acc[0][np * 2],     a0, bb);
                mma_f16(acc[1][np * 2],     a1, bb);
                mma_f16(acc[0][np * 2 + 1], a0, bb + 2);
                mma_f16(acc[1][np * 2 + 1], a1, bb + 2);
            }
        }
        __syncthreads();
    }
    #pragma unroll
    for (int mt = 0; mt < 2; mt++)
        #pragma unroll
        for (int nt = 0; nt < 8; nt++) {
            const int r = wm * 32 + mt * 16 + grp;
            const int c = wn * 64 + nt * 8 + tig * 2;
            const float b0 = conv_b[otile + c], b1 = conv_b[otile + c + 1];
            *(__half2*)(g_xc + (size_t)(mtile + r) * INNER + otile + c) =
                __floats2half2_rn(acc[mt][nt][0] + b0, acc[mt][nt][1] + b1);
            *(__half2*)(g_xc + (size_t)(mtile + r + 8) * INNER + otile + c) =
                __floats2half2_rn(acc[mt][nt][2] + b0, acc[mt][nt][3] + b1);
        }
}

// ---------------- MLP: fp16 mma + ldmatrix, TMA 3-buffer ring, 2 CTA/SM ---------
template <int MODE>
__global__ __launch_bounds__(256, 2) void k_mlp(
    const __grid_constant__ CUtensorMap mA,
    const __grid_constant__ CUtensorMap mB,
    const float* __restrict__ bias,
    float* __restrict__ out_ext) {
    constexpr int K = MODE ? CC : INNER;
    constexpr int NS = K / 64;
    extern __shared__ __align__(1024) char smc[];
    const unsigned sbase = smem_u32(smc);
    const int tid = threadIdx.x, lane = tid & 31, wid = tid >> 5;
    const int wm = wid & 3, wn = wid >> 2;
    const int grp = lane >> 2, tig = lane & 3;
    const int otile = blockIdx.x * 128, m0 = blockIdx.y * 128;

    if (tid == 0) { mb_init(sbase, 1); mb_init(sbase + 8, 1); mb_init(sbase + 16, 1); }
    __syncthreads();

    const int a_r = (lane & 7) + ((lane >> 3) & 1) * 8;
    const unsigned a_kb = (lane >> 4) * 16;
    const unsigned axor = (unsigned)(a_r & 7) << 4;
    const int b_r = (lane & 7) + (lane >> 4) * 8;
    const unsigned b_kb = ((lane >> 3) & 1) * 16;
    const unsigned bxor = (unsigned)(b_r & 7) << 4;
    const unsigned Abase0 = sbase + 1024;
    const unsigned Bbase0 = sbase + 50176;

    float acc[2][8][4] = {};

    auto issue = [&](int s) {
        const int p = s % 3;
        mb_expect(sbase + p * 8, 32768);
        tma2d(Abase0 + p * 16384, &mA, s * 64, m0, sbase + p * 8);
        tma2d(Bbase0 + p * 16384, &mB, s * 64, otile, sbase + p * 8);
    };

    if (tid == 0) { issue(0); if (NS > 1) issue(1); }
    for (int s = 0; s < NS; s++) {
        const int p = s % 3;
        if (s + 2 < NS && tid == 0) issue(s + 2);
        mb_wait(sbase + p * 8, (s / 3) & 1);
        const unsigned Ab = Abase0 + p * 16384;
        const unsigned Bb = Bbase0 + p * 16384;
        #pragma unroll
        for (int ks = 0; ks < 4; ks++) {
            const unsigned ak = ((unsigned)(ks * 32) + a_kb) ^ axor;
            const unsigned bk = ((unsigned)(ks * 32) + b_kb) ^ bxor;
            unsigned a0[4], a1[4];
            lm4(a0, Ab + (unsigned)(wm * 32 + a_r) * 128 + ak);
            lm4(a1, Ab + (unsigned)(wm * 32 + 16 + a_r) * 128 + ak);
            #pragma unroll
            for (int np = 0; np < 4; np++) {
                unsigned bb[4];
                lm4(bb, Bb + (unsigned)(wn * 64 + np * 16 + b_r) * 128 + bk);
                mma_f16(acc[0][np * 2],     a0, bb);
                mma_f16(acc[1][np * 2],     a1, bb);
                mma_f16(acc[0][np * 2 + 1], a0, bb + 2);
                mma_f16(acc[1][np * 2 + 1], a1, bb + 2);
            }
        }
        __syncthreads();
    }
    #pragma unroll
    for (int mt = 0; mt < 2; mt++)
        #pragma unroll
        for (int nt = 0; nt < 8; nt++) {
            const int r = wm * 32 + mt * 16 + grp;
            const int c = wn * 64 + nt * 8 + tig * 2;
            const float b0 = bias[otile + c], b1 = bias[otile + c + 1];
            float v[4] = {acc[mt][nt][0] + b0, acc[mt][nt][1] + b1,
                          acc[mt][nt][2] + b0, acc[mt][nt][3] + b1};
            if (MODE == 0) {
                #pragma unroll
                for (int j = 0; j < 4; j++)
                    v[j] = 0.5f * v[j] * (1.0f + erff(v[j] * 0.70710678118654752f));
                *(__half2*)(g_h1 + (size_t)(m0 + r) * CC + otile + c) =
                    __floats2half2_rn(v[0], v[1]);
                *(__half2*)(g_h1 + (size_t)(m0 + r + 8) * CC + otile + c) =
                    __floats2half2_rn(v[2], v[3]);
            } else {
                *(float2*)(out_ext + (size_t)(m0 + r) * CC + otile + c) =
                    make_float2(v[0], v[1]);
                *(float2*)(out_ext + (size_t)(m0 + r + 8) * CC + otile + c) =
                    make_float2(v[2], v[3]);
            }
        }
}

// ---------------- k_kv: fp16 split mma, ldmatrix, double-buffered X ------------
__global__ __launch_bounds__(256) void k_kv() {
    extern __shared__ __half sh[];
    __half *Xs0 = sh, *Xs1 = sh + 4608;
    __half *Wkh = sh + 9216,  *Wkl = sh + 13824;
    __half *Wvh = sh + 18432, *Wvl = sh + 23040;
    __half *Kth = sh + 27648, *Ktl = sh + 32256;
    __half *Vth = sh + 36864, *Vtl = sh + 41472;

    const int tid = threadIdx.x, lane = tid & 31, wid = tid >> 5;
    const int wm = wid & 3, wn = wid >> 2;
    const int grp = lane >> 2, tig = lane & 3;
    const int bh = blockIdx.y, b = bh >> 3, h = bh & 7;
    const int r = tid >> 2, c0 = (tid & 3) * 16;

    {
        const int gsrc = r * 64 + c0;
        const int sdst = r * 72 + c0;
        *(uint4*)&Wkh[sdst]     = *(const uint4*)&g_wkh[gsrc];
        *(uint4*)&Wkh[sdst + 8] = *(const uint4*)&g_wkh[gsrc + 8];
        *(uint4*)&Wkl[sdst]     = *(const uint4*)&g_wkl[gsrc];
        *(uint4*)&Wkl[sdst + 8] = *(const uint4*)&g_wkl[gsrc + 8];
        *(uint4*)&Wvh[sdst]     = *(const uint4*)&g_wvh[gsrc];
        *(uint4*)&Wvh[sdst + 8] = *(const uint4*)&g_wvh[gsrc + 8];
        *(uint4*)&Wvl[sdst]     = *(const uint4*)&g_wvl[gsrc];
        *(uint4*)&Wvl[sdst + 8] = *(const uint4*)&g_wvl[gsrc + 8];
    }

    const int la_r = (lane & 7) + ((lane >> 3) & 1) * 8;
    const unsigned a_off = (unsigned)la_r * 144 + (lane >> 4) * 16;
    const int lb_r = (lane & 7) + (lane >> 4) * 8;
    const unsigned b_off = (unsigned)lb_r * 144 + ((lane >> 3) & 1) * 16;
    const unsigned Xs0U = smem_u32(Xs0);
    const unsigned WkhU = smem_u32(Wkh), WklU = smem_u32(Wkl);
    const unsigned WvhU = smem_u32(Wvh), WvlU = smem_u32(Wvl);
    const unsigned KthU = smem_u32(Kth), KtlU = smem_u32(Ktl);
    const unsigned VthU = smem_u32(Vth), VtlU = smem_u32(Vtl);
    const unsigned aTile = (unsigned)(wm * 16) * 144 + a_off;
    const unsigned nb0 = (unsigned)(wn * 32) * 144 + b_off;
    const unsigned nb1 = nb0 + 16u * 144;

    float kvacc[4][4] = {};
    float csum[8] = {};
    const int mrow = wm * 16 + grp;

    for (int ch = 0; ch < 32; ch++) {
        const int n0 = blockIdx.x * 2048 + ch * 64;
        __half* Xc = (ch & 1) ? Xs1 : Xs0;
        {
            const __half* xsrc = g_xc + (size_t)(b * NN + n0 + r) * INNER + h * 64 + c0;
            *(uint4*)&Xc[r * 72 + c0]     = *(const uint4*)xsrc;
            *(uint4*)&Xc[r * 72 + c0 + 8] = *(const uint4*)(xsrc + 8);
        }
        __syncthreads();

        const unsigned XcU = Xs0U + (unsigned)(ch & 1) * 9216;
        float ka[4][4] = {}, va[4][4] = {};
        #pragma unroll
        for (int ks = 0; ks < 4; ks++) {
            const unsigned kcB = (unsigned)ks * 32;
            unsigned a[4];
            lm4(a, XcU + aTile + kcB);
            unsigned kh0[4], kh1[4], kl0[4], kl1[4];
            unsigned vh0[4], vh1[4], vl0[4], vl1[4];
            lm4(kh0, WkhU + nb0 + kcB); lm4(kh1, WkhU + nb1 + kcB);
            lm4(kl0, WklU + nb0 + kcB); lm4(kl1, WklU + nb1 + kcB);
            lm4(vh0, WvhU + nb0 + kcB); lm4(vh1, WvhU + nb1 + kcB);
            lm4(vl0, WvlU + nb0 + kcB); lm4(vl1, WvlU + nb1 + kcB);
            mma_f16(ka[0], a, kh0);     mma_f16(ka[0], a, kl0);
            mma_f16(ka[1], a, kh0 + 2); mma_f16(ka[1], a, kl0 + 2);
            mma_f16(ka[2], a, kh1);     mma_f16(ka[2], a, kl1);
            mma_f16(ka[3], a, kh1 + 2); mma_f16(ka[3], a, kl1 + 2);
            mma_f16(va[0], a, vh0);     mma_f16(va[0], a, vl0);
            mma_f16(va[1], a, vh0 + 2); mma_f16(va[1], a, vl0 + 2);
            mma_f16(va[2], a, vh1);     mma_f16(va[2], a, vl1);
            mma_f16(va[3], a, vh1 + 2); mma_f16(va[3], a, vl1 + 2);
        }
        #pragma unroll
        for (int nt = 0; nt < 4; nt++) {
            const int c = wn * 32 + nt * 8 + tig * 2;
            float e;
            e = __expf(ka[nt][0]); csum[nt*2]   += e; split_h(e, Kth[c*72+mrow],       Ktl[c*72+mrow]);
            e = __expf(ka[nt][1]); csum[nt*2+1] += e; split_h(e, Kth[(c+1)*72+mrow],   Ktl[(c+1)*72+mrow]);
            e = __expf(ka[nt][2]); csum[nt*2]   += e; split_h(e, Kth[c*72+mrow+8],     Ktl[c*72+mrow+8]);
            e = __expf(ka[nt][3]); csum[nt*2+1] += e; split_h(e, Kth[(c+1)*72+mrow+8], Ktl[(c+1)*72+mrow+8]);
            split_h(va[nt][0], Vth[c*72+mrow],       Vtl[c*72+mrow]);
            split_h(va[nt][1], Vth[(c+1)*72+mrow],   Vtl[(c+1)*72+mrow]);
            split_h(va[nt][2], Vth[c*72+mrow+8],     Vtl[c*72+mrow+8]);
            split_h(va[nt][3], Vth[(c+1)*72+mrow+8], Vtl[(c+1)*72+mrow+8]);
        }
        __syncthreads();

        #pragma unroll
        for (int ks = 0; ks < 4; ks++) {
            const unsigned kcB = (unsigned)ks * 32;
            unsigned ah[4], al[4];
            lm4(ah, KthU + aTile + kcB);
            lm4(al, KtlU + aTile + kcB);
            unsigned bh0[4], bh1[4], bl0[4], bl1[4];
            lm4(bh0, VthU + nb0 + kcB); lm4(bh1, VthU + nb1 + kcB);
            lm4(bl0, VtlU + nb0 + kcB); lm4(bl1, VtlU + nb1 + kcB);
            mma_f16(kvacc[0], ah, bh0);     mma_f16(kvacc[0], ah, bl0);     mma_f16(kvacc[0], al, bh0);
            mma_f16(kvacc[1], ah, bh0 + 2); mma_f16(kvacc[1], ah, bl0 + 2); mma_f16(kvacc[1], al, bh0 + 2);
            mma_f16(kvacc[2], ah, bh1);     mma_f16(kvacc[2], ah, bl1);     mma_f16(kvacc[2], al, bh1);
            mma_f16(kvacc[3], ah, bh1 + 2); mma_f16(kvacc[3], ah, bl1 + 2); mma_f16(kvacc[3], al, bh1 + 2);
        }
    }

    float* kvbase = g_kv + (size_t)bh * (KRR * DHH);
    #pragma unroll
    for (int nt = 0; nt < 4; nt++) {
        const int c = wn * 32 + nt * 8 + tig * 2;
        atomicAdd(kvbase + mrow * 64 + c,           kvacc[nt][0]);
        atomicAdd(kvbase + mrow * 64 + c + 1,       kvacc[nt][1]);
        atomicAdd(kvbase + (mrow + 8) * 64 + c,     kvacc[nt][2]);
        atomicAdd(kvbase + (mrow + 8) * 64 + c + 1, kvacc[nt][3]);
    }
    #pragma unroll
    for (int idx = 0; idx < 8; idx++) {
        const int c = wn * 32 + (idx >> 1) * 8 + tig * 2 + (idx & 1);
        atomicAdd(g_colsum + bh * 64 + c, csum[idx]);
    }
}

// ---------------- kv normalize + transpose + split ------------------------------
__global__ void k_kvnorm() {
    int i = blockIdx.x * 256 + threadIdx.x;
    float v = g_kv[i] / g_colsum[i >> 6];
    int bh = i >> 12, kr = (i >> 6) & 63, dh = i & 63;
    __half hi, lo;
    split_h(v, hi, lo);
    int o = bh * 4096 + dh * 64 + kr;
    g_kvth[o] = hi;
    g_kvtl[o] = lo;
}

// ---------------- k_qkv: 4 chunks/block, setup amortized ------------------------
__global__ __launch_bounds__(256) void k_qkv() {
    extern __shared__ __half sh[];
    __half *Xs   = sh;
    __half *Qh   = sh + 9216,  *Ql  = sh + 18432;
    __half *Wqh  = sh + 27648, *Wql = sh + 32256;
    __half *kvth = sh + 36864, *kvtl = sh + 41472;
    float  *rsum = (float*)(sh + 46080);
    float  *inv  = rsum + 128;

    const int tid = threadIdx.x, lane = tid & 31, wid = tid >> 5;
    const int wm = wid & 3, wn = wid >> 2;
    const int grp = lane >> 2, tig = lane & 3;
    const int bh = blockIdx.y, b = bh >> 3, h = bh & 7;

    {
        const int r = tid >> 2, c0 = (tid & 3) * 16;
        const int gsrc = r * 64 + c0;
        const int sdst = r * 72 + c0;
        *(uint4*)&Wqh[sdst]     = *(const uint4*)&g_wqh[gsrc];
        *(uint4*)&Wqh[sdst + 8] = *(const uint4*)&g_wqh[gsrc + 8];
        *(uint4*)&Wql[sdst]     = *(const uint4*)&g_wql[gsrc];
        *(uint4*)&Wql[sdst + 8] = *(const uint4*)&g_wql[gsrc + 8];
        const __half* kvh = g_kvth + bh * 4096 + gsrc;
        const __half* kvl = g_kvtl + bh * 4096 + gsrc;
        *(uint4*)&kvth[sdst]     = *(const uint4*)kvh;
        *(uint4*)&kvth[sdst + 8] = *(const uint4*)(kvh + 8);
        *(uint4*)&kvtl[sdst]     = *(const uint4*)kvl;
        *(uint4*)&kvtl[sdst + 8] = *(const uint4*)(kvl + 8);
    }

    const int la_r = (lane & 7) + ((lane >> 3) & 1) * 8;
    const unsigned a_off = (unsigned)la_r * 144 + (lane >> 4) * 16;
    const int lb_r = (lane & 7) + (lane >> 4) * 8;
    const unsigned b_off = (unsigned)lb_r * 144 + ((lane >> 3) & 1) * 16;
    const unsigned XsU = smem_u32(Xs), QhU = smem_u32(Qh), QlU = smem_u32(Ql);
    const unsigned WqhU = smem_u32(Wqh), WqlU = smem_u32(Wql);
    const unsigned kvhU = smem_u32(kvth), kvlU = smem_u32(kvtl);
    const unsigned aT0 = (unsigned)(wm * 32) * 144 + a_off;
    const unsigned aT1 = aT0 + 16u * 144;
    const unsigned nb0 = (unsigned)(wn * 32) * 144 + b_off;
    const unsigned nb1 = nb0 + 16u * 144;
    const int xr = tid >> 1, xc0 = (tid & 1) * 32;

    for (int cch = 0; cch < 4; cch++) {
        const int n0 = blockIdx.x * 512 + cch * 128;
        {
            const __half* xsrc = g_xc + (size_t)(b * NN + n0 + xr) * INNER + h * 64 + xc0;
            #pragma unroll
            for (int j = 0; j < 4; j++)
                *(uint4*)&Xs[xr * 72 + xc0 + j * 8] = *(const uint4*)(xsrc + j * 8);
        }
        if (tid < 128) rsum[tid] = 0.f;
        __syncthreads();

        float qa[2][4][4] = {};
        #pragma unroll
        for (int ks = 0; ks < 4; ks++) {
            const unsigned kcB = (unsigned)ks * 32;
            unsigned a0[4], a1[4];
            lm4(a0, XsU + aT0 + kcB);
            lm4(a1, XsU + aT1 + kcB);
            unsigned qh0[4], qh1[4], ql0[4], ql1[4];
            lm4(qh0, WqhU + nb0 + kcB); lm4(qh1, WqhU + nb1 + kcB);
            lm4(ql0, WqlU + nb0 + kcB); lm4(ql1, WqlU + nb1 + kcB);
            mma_f16(qa[0][0], a0, qh0);     mma_f16(qa[0][0], a0, ql0);
            mma_f16(qa[1][0], a1, qh0);     mma_f16(qa[1][0], a1, ql0);
            mma_f16(qa[0][1], a0, qh0 + 2); mma_f16(qa[0][1], a0, ql0 + 2);
            mma_f16(qa[1][1], a1, qh0 + 2); mma_f16(qa[1][1], a1, ql0 + 2);
            mma_f16(qa[0][2], a0, qh1);     mma_f16(qa[0][2], a0, ql1);
            mma_f16(qa[1][2], a1, qh1);     mma_f16(qa[1][2], a1, ql1);
            mma_f16(qa[0][3], a0, qh1 + 2); mma_f16(qa[0][3], a0, ql1 + 2);
            mma_f16(qa[1][3], a1, qh1 + 2); mma_f16(qa[1][3], a1, ql1 + 2);
        }
        float rp[2][2] = {};
        #pragma unroll
        for (int mt = 0; mt < 2; mt++)
            #pragma unroll
            for (int nt = 0; nt < 4; nt++) {
                const int r = wm * 32 + mt * 16 + grp;
                const int c = wn * 32 + nt * 8 + tig * 2;
                float e0 = __expf(qa[mt][nt][0]), e1 = __expf(qa[mt][nt][1]);
                float e2 = __expf(qa[mt][nt][2]), e3 = __expf(qa[mt][nt][3]);
                rp[mt][0] += e0 + e1; rp[mt][1] += e2 + e3;
                __half h0, l0, h1, l1;
                split_h(e0, h0, l0); split_h(e1, h1, l1);
                *(__half2*)&Qh[r * 72 + c] = __halves2half2(h0, h1);
                *(__half2*)&Ql[r * 72 + c] = __halves2half2(l0, l1);
                split_h(e2, h0, l0); split_h(e3, h1, l1);
                *(__half2*)&Qh[(r + 8) * 72 + c] = __halves2half2(h0, h1);
                *(__half2*)&Ql[(r + 8) * 72 + c] = __halves2half2(l0, l1);
            }
        #pragma unroll
        for (int mt = 0; mt < 2; mt++)
            #pragma unroll
            for (int p = 0; p < 2; p++) {
                float v = rp[mt][p];
                v += __shfl_xor_sync(0xffffffffu, v, 1);
                v += __shfl_xor_sync(0xffffffffu, v, 2);
                if (tig == 0) atomicAdd(&rsum[wm * 32 + mt * 16 + grp + p * 8], v);
            }
        __syncthreads();
        if (tid < 128) inv[tid] = 1.f / rsum[tid];
        __syncthreads();

        float acc[2][4][4] = {};
        #pragma unroll
        for (int ks = 0; ks < 4; ks++) {
            const unsigned kcB = (unsigned)ks * 32;
            unsigned ah0[4], ah1[4], al0[4], al1[4];
            lm4(ah0, QhU + aT0 + kcB); lm4(ah1, QhU + aT1 + kcB);
            lm4(al0, QlU + aT0 + kcB); lm4(al1, QlU + aT1 + kcB);
            unsigned bh0[4], bh1[4], bl0[4], bl1[4];
            lm4(bh0, kvhU + nb0 + kcB); lm4(bh1, kvhU + nb1 + kcB);
            lm4(bl0, kvlU + nb0 + kcB); lm4(bl1, kvlU + nb1 + kcB);
            mma_f16(acc[0][0], ah0, bh0);     mma_f16(acc[0][0], ah0, bl0);     mma_f16(acc[0][0], al0, bh0);
            mma_f16(acc[1][0], ah1, bh0);     mma_f16(acc[1][0], ah1, bl0);     mma_f16(acc[1][0], al1, bh0);
            mma_f16(acc[0][1], ah0, bh0 + 2); mma_f16(acc[0][1], ah0, bl0 + 2); mma_f16(acc[0][1], al0, bh0 + 2);
            mma_f16(acc[1][1], ah1, bh0 + 2); mma_f16(acc[1][1], ah1, bl0 + 2); mma_f16(acc[1][1], al1, bh0 + 2);
            mma_f16(acc[0][2], ah0, bh1);     mma_f16(acc[0][2], ah0, bl1);     mma_f16(acc[0][2], al0, bh1);
            mma_f16(acc[1][2], ah1, bh1);     mma_f16(acc[1][2], ah1, bl1);     mma_f16(acc[1][2], al1, bh1);
            mma_f16(acc[0][3], ah0, bh1 + 2); mma_f16(acc[0][3], ah0, bl1 + 2); mma_f16(acc[0][3], al0, bh1 + 2);
            mma_f16(acc[1][3], ah1, bh1 + 2); mma_f16(acc[1][3], ah1, bl1 + 2); mma_f16(acc[1][3], al1, bh1 + 2);
        }
        #pragma unroll
        for (int mt = 0; mt < 2; mt++)
            #pragma unroll
            for (int nt = 0; nt < 4; nt++) {
                const int r = wm * 32 + mt * 16 + grp;
                const int c = wn * 32 + nt * 8 + tig * 2;
                const float i0 = inv[r], i1 = inv[r + 8];
                __half* d0 = g_qkv + (size_t)(b * NN + n0 + r) * INNER + h * 64 + c;
                __half* d1 = g_qkv + (size_t)(b * NN + n0 + r + 8) * INNER + h * 64 + c;
                *(__half2*)d0 = __floats2half2_rn(acc[mt][nt][0] * i0, acc[mt][nt][1] * i0);
                *(__half2*)d1 = __floats2half2_rn(acc[mt][nt][2] * i1, acc[mt][nt][3] * i1);
            }
        __syncthreads();
    }
}

// ------------------------------------------------------------------------------
extern "C" void kernel_launch(void* const* d_in, const int* in_sizes, int n_in,
                              void* d_out, int out_size) {
    const float* x      = (const float*)d_in[0];
    const float* conv_w = (const float*)d_in[1];
    const float* conv_b = (const float*)d_in[2];
    const float* Wq     = (const float*)d_in[3];
    const float* Wk     = (const float*)d_in[4];
    const float* Wv     = (const float*)d_in[5];
    const float* W1     = (const float*)d_in[6];
    const float* b1     = (const float*)d_in[7];
    const float* W2     = (const float*)d_in[8];
    const float* b2     = (const float*)d_in[9];
    float* out = (float*)d_out;

    using EncFn = decltype(&cuTensorMapEncodeTiled);
    static EncFn enc = nullptr;
    if (!enc) {
        void* fp = nullptr;
        cudaDriverEntryPointQueryResult qr;
        cudaGetDriverEntryPointByVersion("cuTensorMapEncodeTiled", &fp, 12000,
                                         cudaEnableDefault, &qr);
        enc = (EncFn)fp;
    }
    static CUtensorMap mCA, mCB, mA0, mB0, mA1, mB1;
    {
        void *xp, *wp, *qkvp, *w1p, *h1p, *w2p;
        cudaGetSymbolAddress(&xp, g_xh);
        cudaGetSymbolAddress(&wp, g_wch);
        cudaGetSymbolAddress(&qkvp, g_qkv);
        cudaGetSymbolAddress(&w1p, g_w1h);
        cudaGetSymbolAddress(&h1p, g_h1);
        cudaGetSymbolAddress(&w2p, g_w2h);
        cuuint32_t e4[4] = {1, 1, 1, 1};
        cuuint64_t dA[4] = {256, 128, 128, 8};
        cuuint64_t sA[3] = {512, 65536, 8388608};
        cuuint32_t bA[4] = {64, 128, 1, 1};
        enc(&mCA, CU_TENSOR_MAP_DATA_TYPE_FLOAT16, 4, xp, dA, sA, bA, e4,
            CU_TENSOR_MAP_INTERLEAVE_NONE, CU_TENSOR_MAP_SWIZZLE_128B,
            CU_TENSOR_MAP_L2_PROMOTION_L2_128B, CU_TENSOR_MAP_FLOAT_OOB_FILL_NONE);
        cuuint64_t dB[2] = {KCONV, INNER};
        cuuint64_t sB[1] = {KCONV * 2};
        cuuint32_t bB[2] = {64, 128};
        enc(&mCB, CU_TENSOR_MAP_DATA_TYPE_FLOAT16, 2, wp, dB, sB, bB, e4,
            CU_TENSOR_MAP_INTERLEAVE_NONE, CU_TENSOR_MAP_SWIZZLE_128B,
            CU_TENSOR_MAP_L2_PROMOTION_L2_128B, CU_TENSOR_MAP_FLOAT_OOB_FILL_NONE);
        cuuint64_t dA0[2] = {512, 131072}; cuuint64_t sA0[1] = {1024};
        enc(&mA0, CU_TENSOR_MAP_DATA_TYPE_FLOAT16, 2, qkvp, dA0, sA0, bB, e4,
            CU_TENSOR_MAP_INTERLEAVE_NONE, CU_TENSOR_MAP_SWIZZLE_128B,
            CU_TENSOR_MAP_L2_PROMOTION_L2_128B, CU_TENSOR_MAP_FLOAT_OOB_FILL_NONE);
        cuuint64_t dB0[2] = {512, 256}; cuuint64_t sB0[1] = {1024};
        enc(&mB0, CU_TENSOR_MAP_DATA_TYPE_FLOAT16, 2, w1p, dB0, sB0, bB, e4,
            CU_TENSOR_MAP_INTERLEAVE_NONE, CU_TENSOR_MAP_SWIZZLE_128B,
            CU_TENSOR_MAP_L2_PROMOTION_L2_128B, CU_TENSOR_MAP_FLOAT_OOB_FILL_NONE);
        cuuint64_t dA1[2] = {256, 131072}; cuuint64_t sA1[1] = {512};
        enc(&mA1, CU_TENSOR_MAP_DATA_TYPE_FLOAT16, 2, h1p, dA1, sA1, bB, e4,
            CU_TENSOR_MAP_INTERLEAVE_NONE, CU_TENSOR_MAP_SWIZZLE_128B,
            CU_TENSOR_MAP_L2_PROMOTION_L2_128B, CU_TENSOR_MAP_FLOAT_OOB_FILL_NONE);
        cuuint64_t dB1[2] = {256, 256}; cuuint64_t sB1[1] = {512};
        enc(&mB1, CU_TENSOR_MAP_DATA_TYPE_FLOAT16, 2, w2p, dB1, sB1, bB, e4,
            CU_TENSOR_MAP_INTERLEAVE_NONE, CU_TENSOR_MAP_SWIZZLE_128B,
            CU_TENSOR_MAP_L2_PROMOTION_L2_128B, CU_TENSOR_MAP_FLOAT_OOB_FILL_NONE);
    }

    cudaFuncSetAttribute(k_conv, cudaFuncAttributeMaxDynamicSharedMemorySize, 99328);
    cudaFuncSetAttribute(k_mlp<0>, cudaFuncAttributeMaxDynamicSharedMemorySize, 99328);
    cudaFuncSetAttribute(k_mlp<1>, cudaFuncAttributeMaxDynamicSharedMemorySize, 99328);
    cudaFuncSetAttribute(k_kv,   cudaFuncAttributeMaxDynamicSharedMemorySize, 92160);
    cudaFuncSetAttribute(k_qkv,  cudaFuncAttributeMaxDynamicSharedMemorySize, 93184);

    k_prep<<<(BB * NN * CC) / 4 / 256, 256>>>(x, conv_w, W1, W2, Wq, Wk, Wv);
    k_conv<<<dim3(INNER / 128, (BB * NN) / 128), 256, 99328>>>(mCA, mCB, conv_b);
    k_kv<<<dim3(8, BB * HEADS), 256, 92160>>>();
    k_kvnorm<<<(BB * HEADS * KRR * DHH) / 256, 256>>>();
    k_qkv<<<dim3(32, BB * HEADS), 256, 93184>>>();
    k_mlp<0><<<dim3(CC / 128, (BB * NN) / 128), 256, 99328>>>(mA0, mB0, b1, nullptr);
    k_mlp<1><<<dim3(CC / 128, (BB * NN) / 128), 256, 99328>>>(mA1, mB1, b2, out);
}

// round 16
// speedup vs baseline: 1.1457x; 1.0122x over previous
#include <cuda_runtime.h>
#include <cuda.h>
#include <cuda_fp16.h>
#include <math.h>

#define BB 8
#define CC 256
#define NN 16384
#define HEADS 8
#define INNER 512
#define KCONV 2304
#define KRR 64
#define DHH 64

__device__ __half g_wch[(size_t)INNER * KCONV];
__device__ __half g_xh[(size_t)BB * NN * CC];
__device__ __half g_w1h[CC * INNER];
__device__ __half g_w2h[CC * CC];
__device__ __half g_xc[(size_t)BB * NN * INNER];
__device__ float  g_colsum[BB * HEADS * KRR];
__device__ float  g_kv[BB * HEADS * KRR * DHH];
__device__ __half g_qkv[(size_t)BB * NN * INNER];
__device__ __half g_h1[(size_t)BB * NN * CC];
__device__ __half g_wqh[4096], g_wql[4096], g_wkh[4096], g_wkl[4096];
__device__ __half g_wvh[4096], g_wvl[4096];
__device__ __half g_kvth[64 * 4096], g_kvtl[64 * 4096];   // [bh][dh][kr]

__device__ __forceinline__ void mma_f16(float c[4], const unsigned a[4], const unsigned b[2]) {
    asm volatile("mma.sync.aligned.m16n8k16.row.col.f32.f16.f16.f32 "
        "{%0,%1,%2,%3}, {%4,%5,%6,%7}, {%8,%9}, {%0,%1,%2,%3};"
        : "+f"(c[0]), "+f"(c[1]), "+f"(c[2]), "+f"(c[3])
        : "r"(a[0]), "r"(a[1]), "r"(a[2]), "r"(a[3]), "r"(b[0]), "r"(b[1]));
}
__device__ __forceinline__ void lm4(unsigned r[4], unsigned a) {
    asm volatile("ldmatrix.sync.aligned.m8n8.x4.shared.b16 {%0,%1,%2,%3}, [%4];"
        : "=r"(r[0]), "=r"(r[1]), "=r"(r[2]), "=r"(r[3]) : "r"(a));
}
__device__ __forceinline__ void split_h(float f, __half& hi, __half& lo) {
    hi = __float2half_rn(f);
    lo = __float2half_rn(f - __half2float(hi));
}
__device__ __forceinline__ unsigned smem_u32(const void* p) {
    return (unsigned)__cvta_generic_to_shared(p);
}
__device__ __forceinline__ void mb_init(unsigned a, unsigned n) {
    asm volatile("mbarrier.init.shared.b64 [%0], %1;" :: "r"(a), "r"(n) : "memory");
}
__device__ __forceinline__ void mb_expect(unsigned a, unsigned bytes) {
    asm volatile("mbarrier.arrive.expect_tx.shared.b64 _, [%0], %1;"
                 :: "r"(a), "r"(bytes) : "memory");
}
__device__ __forceinline__ void mb_wait(unsigned a, unsigned ph) {
    asm volatile("{\n\t.reg .pred P;\n\tW%=:\n\t"
                 "mbarrier.try_wait.parity.shared.b64 P, [%0], %1;\n\t"
                 "@!P bra W%=;\n\t}" :: "r"(a), "r"(ph) : "memory");
}
__device__ __forceinline__ void tma4d(unsigned dst, const CUtensorMap* m,
                                      int c0, int c1, int c2, int c3, unsigned mb) {
    asm volatile("cp.async.bulk.tensor.4d.shared::cta.global.tile.mbarrier::complete_tx::bytes"
                 " [%0], [%1, {%2,%3,%4,%5}], [%6];"
                 :: "r"(dst), "l"(m), "r"(c0), "r"(c1), "r"(c2), "r"(c3), "r"(mb) : "memory");
}
__device__ __forceinline__ void tma2d(unsigned dst, const CUtensorMap* m,
                                      int c0, int c1, unsigned mb) {
    asm volatile("cp.async.bulk.tensor.2d.shared::cta.global.tile.mbarrier::complete_tx::bytes"
                 " [%0], [%1, {%2,%3}], [%4];"
                 :: "r"(dst), "l"(m), "r"(c0), "r"(c1), "r"(mb) : "memory");
}

// ---------------- fused prep (grid covers ALL of x: 8388608 float4s) ------------
__global__ void k_prep(const float* __restrict__ x, const float* __restrict__ conv_w,
                       const float* __restrict__ W1, const float* __restrict__ W2,
                       const float* __restrict__ Wq, const float* __restrict__ Wk,
                       const float* __restrict__ Wv) {
    int t = blockIdx.x * 256 + threadIdx.x;            // 0 .. 8388607
    float4 v = ((const float4*)x)[t];
    ((__half2*)g_xh)[t * 2]     = __floats2half2_rn(v.x, v.y);
    ((__half2*)g_xh)[t * 2 + 1] = __floats2half2_rn(v.z, v.w);
    if (t < INNER * KCONV) {
        int o = t / KCONV, k = t - o * KCONV;
        g_wch[t] = __float2half_rn(conv_w[(size_t)(o * CC + (k & 255)) * 9 + (k >> 8)]);
    }
    if (t < BB * HEADS * KRR * DHH) g_kv[t] = 0.f;
    if (t < CC * INNER) g_w1h[t] = __float2half_rn(W1[t]);
    if (t < CC * CC)    g_w2h[t] = __float2half_rn(W2[t]);
    if (t < BB * HEADS * KRR) g_colsum[t] = 0.f;
    if (t < 4096) {
        split_h(Wq[t], g_wqh[t], g_wql[t]);
        split_h(Wk[t], g_wkh[t], g_wkl[t]);
        split_h(Wv[t], g_wvh[t], g_wvl[t]);
    }
}

// ---------------- conv: fp16 mma + ldmatrix, TMA 2-buffer, 2 CTA/SM -------------
__global__ __launch_bounds__(256, 2) void k_conv(
    const __grid_constant__ CUtensorMap mA,
    const __grid_constant__ CUtensorMap mB,
    const float* __restrict__ conv_b) {
    extern __shared__ __align__(1024) char smc[];
    const unsigned sbase = smem_u32(smc);
    const int tid = threadIdx.x, lane = tid & 31, wid = tid >> 5;
    const int wm = wid & 3, wn = wid >> 2;
    const int grp = lane >> 2, tig = lane & 3;
    const int otile = blockIdx.x * 128, mtile = blockIdx.y * 128;
    const int b = mtile >> 14;
    const int py = (mtile & (NN - 1)) >> 7;

    if (tid == 0) { mb_init(sbase, 1); mb_init(sbase + 8, 1); }
    __syncthreads();

    const int a_r = (lane & 7) + ((lane >> 3) & 1) * 8;
    const unsigned a_kb = (lane >> 4) * 16;
    const unsigned axor = (unsigned)(a_r & 7) << 4;
    const int b_r = (lane & 7) + (lane >> 4) * 8;
    const unsigned b_kb = ((lane >> 3) & 1) * 16;
    const unsigned bxor = (unsigned)(b_r & 7) << 4;
    const unsigned Abase0 = sbase + 1024;
    const unsigned Bbase0 = sbase + 33792;

    float acc[2][8][4] = {};

    auto issue = [&](int s) {
        const int p = s & 1;
        const int g = s >> 2;
        const int dy = g / 3 - 1, dx = g % 3 - 1;
        const int cb = (s & 3) * 64;
        mb_expect(sbase + p * 8, 32768);
        tma4d(Abase0 + p * 16384, &mA, cb, dx, py + dy, b, sbase + p * 8);
        tma2d(Bbase0 + p * 16384, &mB, g * 256 + cb, otile, sbase + p * 8);
    };

    if (tid == 0) issue(0);
    for (int s = 0; s < 36; s++) {
        const int p = s & 1;
        if (s + 1 < 36 && tid == 0) issue(s + 1);
        mb_wait(sbase + p * 8, (s >> 1) & 1);
        const unsigned Ab = Abase0 + p * 16384;
        const unsigned Bb = Bbase0 + p * 16384;
        #pragma unroll
        for (int ks = 0; ks < 4; ks++) {
            const unsigned ak = ((unsigned)(ks * 32) + a_kb) ^ axor;
            const unsigned bk = ((unsigned)(ks * 32) + b_kb) ^ bxor;
            unsigned a0[4], a1[4];
            lm4(a0, Ab + (unsigned)(wm * 32 + a_r) * 128 + ak);
            lm4(a1, Ab + (unsigned)(wm * 32 + 16 + a_r) * 128 + ak);
            #pragma unroll
            for (int np = 0; np < 4; np++) {
                unsigned bb[4];
                lm4(bb, Bb + (unsigned)(wn * 64 + np * 16 + b_r) * 128 + bk);
                mma_f16(acc[0][np * 2],     a0, bb);
                mma_f16(acc[1][np * 2],     a1, bb);
                mma_f16(acc[0][np * 2 + 1], a0, bb + 2);
                mma_f16(acc[1][np * 2 + 1], a1, bb + 2);
            }
        }
        __syncthreads();
    }
    #pragma unroll
    for (int mt = 0; mt < 2; mt++)
        #pragma unroll
        for (int nt = 0; nt < 8; nt++) {
            const int r = wm * 32 + mt * 16 + grp;
            const int c = wn * 64 + nt * 8 + tig * 2;
            const float b0 = conv_b[otile + c], b1 = conv_b[otile + c + 1];
            *(__half2*)(g_xc + (size_t)(mtile + r) * INNER + otile + c) =
                __floats2half2_rn(acc[mt][nt][0] + b0, acc[mt][nt][1] + b1);
            *(__half2*)(g_xc + (size_t)(mtile + r + 8) * INNER + otile + c) =
                __floats2half2_rn(acc[mt][nt][2] + b0, acc[mt][nt][3] + b1);
        }
}

// ---------------- MLP: fp16 mma + ldmatrix, TMA 2-buffer, 2 CTA/SM --------------
template <int MODE>
__global__ __launch_bounds__(256, 2) void k_mlp(
    const __grid_constant__ CUtensorMap mA,
    const __grid_constant__ CUtensorMap mB,
    const float* __restrict__ bias,
    float* __restrict__ out_ext) {
    constexpr int K = MODE ? CC : INNER;
    constexpr int NS = K / 64;
    extern __shared__ __align__(1024) char smc[];
    const unsigned sbase = smem_u32(smc);
    const int tid = threadIdx.x, lane = tid & 31, wid = tid >> 5;
    const int wm = wid & 3, wn = wid >> 2;
    const int grp = lane >> 2, tig = lane & 3;
    const int otile = blockIdx.x * 128, m0 = blockIdx.y * 128;

    if (tid == 0) { mb_init(sbase, 1); mb_init(sbase + 8, 1); }
    __syncthreads();

    const int a_r = (lane & 7) + ((lane >> 3) & 1) * 8;
    const unsigned a_kb = (lane >> 4) * 16;
    const unsigned axor = (unsigned)(a_r & 7) << 4;
    const int b_r = (lane & 7) + (lane >> 4) * 8;
    const unsigned b_kb = ((lane >> 3) & 1) * 16;
    const unsigned bxor = (unsigned)(b_r & 7) << 4;
    const unsigned Abase0 = sbase + 1024;
    const unsigned Bbase0 = sbase + 33792;

    float acc[2][8][4] = {};

    auto issue = [&](int s) {
        const int p = s & 1;
        mb_expect(sbase + p * 8, 32768);
        tma2d(Abase0 + p * 16384, &mA, s * 64, m0, sbase + p * 8);
        tma2d(Bbase0 + p * 16384, &mB, s * 64, otile, sbase + p * 8);
    };

    if (tid == 0) issue(0);
    for (int s = 0; s < NS; s++) {
        const int p = s & 1;
        if (s + 1 < NS && tid == 0) issue(s + 1);
        mb_wait(sbase + p * 8, (s >> 1) & 1);
        const unsigned Ab = Abase0 + p * 16384;
        const unsigned Bb = Bbase0 + p * 16384;
        #pragma unroll
        for (int ks = 0; ks < 4; ks++) {
            const unsigned ak = ((unsigned)(ks * 32) + a_kb) ^ axor;
            const unsigned bk = ((unsigned)(ks * 32) + b_kb) ^ bxor;
            unsigned a0[4], a1[4];
            lm4(a0, Ab + (unsigned)(wm * 32 + a_r) * 128 + ak);
            lm4(a1, Ab + (unsigned)(wm * 32 + 16 + a_r) * 128 + ak);
            #pragma unroll
            for (int np = 0; np < 4; np++) {
                unsigned bb[4];
                lm4(bb, Bb + (unsigned)(wn * 64 + np * 16 + b_r) * 128 + bk);
                mma_f16(acc[0][np * 2],     a0, bb);
                mma_f16(acc[1][np * 2],     a1, bb);
                mma_f16(acc[0][np * 2 + 1], a0, bb + 2);
                mma_f16(acc[1][np * 2 + 1], a1, bb + 2);
            }
        }
        __syncthreads();
    }
    #pragma unroll
    for (int mt = 0; mt < 2; mt++)
        #pragma unroll
        for (int nt = 0; nt < 8; nt++) {
            const int r = wm * 32 + mt * 16 + grp;
            const int c = wn * 64 + nt * 8 + tig * 2;
            const float b0 = bias[otile + c], b1 = bias[otile + c + 1];
            float v[4] = {acc[mt][nt][0] + b0, acc[mt][nt][1] + b1,
                          acc[mt][nt][2] + b0, acc[mt][nt][3] + b1};
            if (MODE == 0) {
                #pragma unroll
                for (int j = 0; j < 4; j++)
                    v[j] = 0.5f * v[j] * (1.0f + erff(v[j] * 0.70710678118654752f));
                *(__half2*)(g_h1 + (size_t)(m0 + r) * CC + otile + c) =
                    __floats2half2_rn(v[0], v[1]);
                *(__half2*)(g_h1 + (size_t)(m0 + r + 8) * CC + otile + c) =
                    __floats2half2_rn(v[2], v[3]);
            } else {
                *(float2*)(out_ext + (size_t)(m0 + r) * CC + otile + c) =
                    make_float2(v[0], v[1]);
                *(float2*)(out_ext + (size_t)(m0 + r + 8) * CC + otile + c) =
                    make_float2(v[2], v[3]);
            }
        }
}

// ---------------- k_kv: fp16 split mma, ldmatrix, double-buffered X ------------
__global__ __launch_bounds__(256) void k_kv() {
    extern __shared__ __half sh[];
    __half *Xs0 = sh, *Xs1 = sh + 4608;
    __half *Wkh = sh + 9216,  *Wkl = sh + 13824;
    __half *Wvh = sh + 18432, *Wvl = sh + 23040;
    __half *Kth = sh + 27648, *Ktl = sh + 32256;
    __half *Vth = sh + 36864, *Vtl = sh + 41472;

    const int tid = threadIdx.x, lane = tid & 31, wid = tid >> 5;
    const int wm = wid & 3, wn = wid >> 2;
    const int grp = lane >> 2, tig = lane & 3;
    const int bh = blockIdx.y, b = bh >> 3, h = bh & 7;
    const int r = tid >> 2, c0 = (tid & 3) * 16;

    {
        const int gsrc = r * 64 + c0;
        const int sdst = r * 72 + c0;
        *(uint4*)&Wkh[sdst]     = *(const uint4*)&g_wkh[gsrc];
        *(uint4*)&Wkh[sdst + 8] = *(const uint4*)&g_wkh[gsrc + 8];
        *(uint4*)&Wkl[sdst]     = *(const uint4*)&g_wkl[gsrc];
        *(uint4*)&Wkl[sdst + 8] = *(const uint4*)&g_wkl[gsrc + 8];
        *(uint4*)&Wvh[sdst]     = *(const uint4*)&g_wvh[gsrc];
        *(uint4*)&Wvh[sdst + 8] = *(const uint4*)&g_wvh[gsrc + 8];
        *(uint4*)&Wvl[sdst]     = *(const uint4*)&g_wvl[gsrc];
        *(uint4*)&Wvl[sdst + 8] = *(const uint4*)&g_wvl[gsrc + 8];
    }

    const int la_r = (lane & 7) + ((lane >> 3) & 1) * 8;
    const unsigned a_off = (unsigned)la_r * 144 + (lane >> 4) * 16;
    const int lb_r = (lane & 7) + (lane >> 4) * 8;
    const unsigned b_off = (unsigned)lb_r * 144 + ((lane >> 3) & 1) * 16;
    const unsigned Xs0U = smem_u32(Xs0);
    const unsigned WkhU = smem_u32(Wkh), WklU = smem_u32(Wkl);
    const unsigned WvhU = smem_u32(Wvh), WvlU = smem_u32(Wvl);
    const unsigned KthU = smem_u32(Kth), KtlU = smem_u32(Ktl);
    const unsigned VthU = smem_u32(Vth), VtlU = smem_u32(Vtl);
    const unsigned aTile = (unsigned)(wm * 16) * 144 + a_off;
    const unsigned nb0 = (unsigned)(wn * 32) * 144 + b_off;
    const unsigned nb1 = nb0 + 16u * 144;

    float kvacc[4][4] = {};
    float csum[8] = {};
    const int mrow = wm * 16 + grp;

    for (int ch = 0; ch < 32; ch++) {
        const int n0 = blockIdx.x * 2048 + ch * 64;
        __half* Xc = (ch & 1) ? Xs1 : Xs0;
        {
            const __half* xsrc = g_xc + (size_t)(b * NN + n0 + r) * INNER + h * 64 + c0;
            *(uint4*)&Xc[r * 72 + c0]     = *(const uint4*)xsrc;
            *(uint4*)&Xc[r * 72 + c0 + 8] = *(const uint4*)(xsrc + 8);
        }
        __syncthreads();

        const unsigned XcU = Xs0U + (unsigned)(ch & 1) * 9216;
        float ka[4][4] = {}, va[4][4] = {};
        #pragma unroll
        for (int ks = 0; ks < 4; ks++) {
            const unsigned kcB = (unsigned)ks * 32;
            unsigned a[4];
            lm4(a, XcU + aTile + kcB);
            unsigned kh0[4], kh1[4], kl0[4], kl1[4];
            unsigned vh0[4], vh1[4], vl0[4], vl1[4];
            lm4(kh0, WkhU + nb0 + kcB); lm4(kh1, WkhU + nb1 + kcB);
            lm4(kl0, WklU + nb0 + kcB); lm4(kl1, WklU + nb1 + kcB);
            lm4(vh0, WvhU + nb0 + kcB); lm4(vh1, WvhU + nb1 + kcB);
            lm4(vl0, WvlU + nb0 + kcB); lm4(vl1, WvlU + nb1 + kcB);
            mma_f16(ka[0], a, kh0);     mma_f16(ka[0], a, kl0);
            mma_f16(ka[1], a, kh0 + 2); mma_f16(ka[1], a, kl0 + 2);
            mma_f16(ka[2], a, kh1);     mma_f16(ka[2], a, kl1);
            mma_f16(ka[3], a, kh1 + 2); mma_f16(ka[3], a, kl1 + 2);
            mma_f16(va[0], a, vh0);     mma_f16(va[0], a, vl0);
            mma_f16(va[1], a, vh0 + 2); mma_f16(va[1], a, vl0 + 2);
            mma_f16(va[2], a, vh1);     mma_f16(va[2], a, vl1);
            mma_f16(va[3], a, vh1 + 2); mma_f16(va[3], a, vl1 + 2);
        }
        #pragma unroll
        for (int nt = 0; nt < 4; nt++) {
            const int c = wn * 32 + nt * 8 + tig * 2;
            float e;
            e = __expf(ka[nt][0]); csum[nt*2]   += e; split_h(e, Kth[c*72+mrow],       Ktl[c*72+mrow]);
            e = __expf(ka[nt][1]); csum[nt*2+1] += e; split_h(e, Kth[(c+1)*72+mrow],   Ktl[(c+1)*72+mrow]);
            e = __expf(ka[nt][2]); csum[nt*2]   += e; split_h(e, Kth[c*72+mrow+8],     Ktl[c*72+mrow+8]);
            e = __expf(ka[nt][3]); csum[nt*2+1] += e; split_h(e, Kth[(c+1)*72+mrow+8], Ktl[(c+1)*72+mrow+8]);
            split_h(va[nt][0], Vth[c*72+mrow],       Vtl[c*72+mrow]);
            split_h(va[nt][1], Vth[(c+1)*72+mrow],   Vtl[(c+1)*72+mrow]);
            split_h(va[nt][2], Vth[c*72+mrow+8],     Vtl[c*72+mrow+8]);
            split_h(va[nt][3], Vth[(c+1)*72+mrow+8], Vtl[(c+1)*72+mrow+8]);
        }
        __syncthreads();

        #pragma unroll
        for (int ks = 0; ks < 4; ks++) {
            const unsigned kcB = (unsigned)ks * 32;
            unsigned ah[4], al[4];
            lm4(ah, KthU + aTile + kcB);
            lm4(al, KtlU + aTile + kcB);
            unsigned bh0[4], bh1[4], bl0[4], bl1[4];
            lm4(bh0, VthU + nb0 + kcB); lm4(bh1, VthU + nb1 + kcB);
            lm4(bl0, VtlU + nb0 + kcB); lm4(bl1, VtlU + nb1 + kcB);
            mma_f16(kvacc[0], ah, bh0);     mma_f16(kvacc[0], ah, bl0);     mma_f16(kvacc[0], al, bh0);
            mma_f16(kvacc[1], ah, bh0 + 2); mma_f16(kvacc[1], ah, bl0 + 2); mma_f16(kvacc[1], al, bh0 + 2);
            mma_f16(kvacc[2], ah, bh1);     mma_f16(kvacc[2], ah, bl1);     mma_f16(kvacc[2], al, bh1);
            mma_f16(kvacc[3], ah, bh1 + 2); mma_f16(kvacc[3], ah, bl1 + 2); mma_f16(kvacc[3], al, bh1 + 2);
        }
    }

    float* kvbase = g_kv + (size_t)bh * (KRR * DHH);
    #pragma unroll
    for (int nt = 0; nt < 4; nt++) {
        const int c = wn * 32 + nt * 8 + tig * 2;
        atomicAdd(kvbase + mrow * 64 + c,           kvacc[nt][0]);
        atomicAdd(kvbase + mrow * 64 + c + 1,       kvacc[nt][1]);
        atomicAdd(kvbase + (mrow + 8) * 64 + c,     kvacc[nt][2]);
        atomicAdd(kvbase + (mrow + 8) * 64 + c + 1, kvacc[nt][3]);
    }
    #pragma unroll
    for (int idx = 0; idx < 8; idx++) {
        const int c = wn * 32 + (idx >> 1) * 8 + tig * 2 + (idx & 1);
        atomicAdd(g_colsum + bh * 64 + c, csum[idx]);
    }
}

// ---------------- kv normalize + transpose + split ------------------------------
__global__ void k_kvnorm() {
    int i = blockIdx.x * 256 + threadIdx.x;
    float v = g_kv[i] / g_colsum[i >> 6];
    int bh = i >> 12, kr = (i >> 6) & 63, dh = i & 63;
    __half hi, lo;
    split_h(v, hi, lo);
    int o = bh * 4096 + dh * 64 + kr;
    g_kvth[o] = hi;
    g_kvtl[o] = lo;
}

// ---------------- k_qkv: 4 chunks/block, setup amortized ------------------------
__global__ __launch_bounds__(256) void k_qkv() {
    extern __shared__ __half sh[];
    __half *Xs   = sh;
    __half *Qh   = sh + 9216,  *Ql  = sh + 18432;
    __half *Wqh  = sh + 27648, *Wql = sh + 32256;
    __half *kvth = sh + 36864, *kvtl = sh + 41472;
    float  *rsum = (float*)(sh + 46080);
    float  *inv  = rsum + 128;

    const int tid = threadIdx.x, lane = tid & 31, wid = tid >> 5;
    const int wm = wid & 3, wn = wid >> 2;
    const int grp = lane >> 2, tig = lane & 3;
    const int bh = blockIdx.y, b = bh >> 3, h = bh & 7;

    {
        const int r = tid >> 2, c0 = (tid & 3) * 16;
        const int gsrc = r * 64 + c0;
        const int sdst = r * 72 + c0;
        *(uint4*)&Wqh[sdst]     = *(const uint4*)&g_wqh[gsrc];
        *(uint4*)&Wqh[sdst + 8] = *(const uint4*)&g_wqh[gsrc + 8];
        *(uint4*)&Wql[sdst]     = *(const uint4*)&g_wql[gsrc];
        *(uint4*)&Wql[sdst + 8] = *(const uint4*)&g_wql[gsrc + 8];
        const __half* kvh = g_kvth + bh * 4096 + gsrc;
        const __half* kvl = g_kvtl + bh * 4096 + gsrc;
        *(uint4*)&kvth[sdst]     = *(const uint4*)kvh;
        *(uint4*)&kvth[sdst + 8] = *(const uint4*)(kvh + 8);
        *(uint4*)&kvtl[sdst]     = *(const uint4*)kvl;
        *(uint4*)&kvtl[sdst + 8] = *(const uint4*)(kvl + 8);
    }

    const int la_r = (lane & 7) + ((lane >> 3) & 1) * 8;
    const unsigned a_off = (unsigned)la_r * 144 + (lane >> 4) * 16;
    const int lb_r = (lane & 7) + (lane >> 4) * 8;
    const unsigned b_off = (unsigned)lb_r * 144 + ((lane >> 3) & 1) * 16;
    const unsigned XsU = smem_u32(Xs), QhU = smem_u32(Qh), QlU = smem_u32(Ql);
    const unsigned WqhU = smem_u32(Wqh), WqlU = smem_u32(Wql);
    const unsigned kvhU = smem_u32(kvth), kvlU = smem_u32(kvtl);
    const unsigned aT0 = (unsigned)(wm * 32) * 144 + a_off;
    const unsigned aT1 = aT0 + 16u * 144;
    const unsigned nb0 = (unsigned)(wn * 32) * 144 + b_off;
    const unsigned nb1 = nb0 + 16u * 144;
    const int xr = tid >> 1, xc0 = (tid & 1) * 32;

    for (int cch = 0; cch < 4; cch++) {
        const int n0 = blockIdx.x * 512 + cch * 128;
        {
            const __half* xsrc = g_xc + (size_t)(b * NN + n0 + xr) * INNER + h * 64 + xc0;
            #pragma unroll
            for (int j = 0; j < 4; j++)
                *(uint4*)&Xs[xr * 72 + xc0 + j * 8] = *(const uint4*)(xsrc + j * 8);
        }
        if (tid < 128) rsum[tid] = 0.f;
        __syncthreads();

        float qa[2][4][4] = {};
        #pragma unroll
        for (int ks = 0; ks < 4; ks++) {
            const unsigned kcB = (unsigned)ks * 32;
            unsigned a0[4], a1[4];
            lm4(a0, XsU + aT0 + kcB);
            lm4(a1, XsU + aT1 + kcB);
            unsigned qh0[4], qh1[4], ql0[4], ql1[4];
            lm4(qh0, WqhU + nb0 + kcB); lm4(qh1, WqhU + nb1 + kcB);
            lm4(ql0, WqlU + nb0 + kcB); lm4(ql1, WqlU + nb1 + kcB);
            mma_f16(qa[0][0], a0, qh0);     mma_f16(qa[0][0], a0, ql0);
            mma_f16(qa[1][0], a1, qh0);     mma_f16(qa[1][0], a1, ql0);
            mma_f16(qa[0][1], a0, qh0 + 2); mma_f16(qa[0][1], a0, ql0 + 2);
            mma_f16(qa[1][1], a1, qh0 + 2); mma_f16(qa[1][1], a1, ql0 + 2);
            mma_f16(qa[0][2], a0, qh1);     mma_f16(qa[0][2], a0, ql1);
            mma_f16(qa[1][2], a1, qh1);     mma_f16(qa[1][2], a1, ql1);
            mma_f16(qa[0][3], a0, qh1 + 2); mma_f16(qa[0][3], a0, ql1 + 2);
            mma_f16(qa[1][3], a1, qh1 + 2); mma_f16(qa[1][3], a1, ql1 + 2);
        }
        float rp[2][2] = {};
        #pragma unroll
        for (int mt = 0; mt < 2; mt++)
            #pragma unroll
            for (int nt = 0; nt < 4; nt++) {
                const int r = wm * 32 + mt * 16 + grp;
                const int c = wn * 32 + nt * 8 + tig * 2;
                float e0 = __expf(qa[mt][nt][0]), e1 = __expf(qa[mt][nt][1]);
                float e2 = __expf(qa[mt][nt][2]), e3 = __expf(qa[mt][nt][3]);
                rp[mt][0] += e0 + e1; rp[mt][1] += e2 + e3;
                __half h0, l0, h1, l1;
                split_h(e0, h0, l0); split_h(e1, h1, l1);
                *(__half2*)&Qh[r * 72 + c] = __halves2half2(h0, h1);
                *(__half2*)&Ql[r * 72 + c] = __halves2half2(l0, l1);
                split_h(e2, h0, l0); split_h(e3, h1, l1);
                *(__half2*)&Qh[(r + 8) * 72 + c] = __halves2half2(h0, h1);
                *(__half2*)&Ql[(r + 8) * 72 + c] = __halves2half2(l0, l1);
            }
        #pragma unroll
        for (int mt = 0; mt < 2; mt++)
            #pragma unroll
            for (int p = 0; p < 2; p++) {
                float v = rp[mt][p];
                v += __shfl_xor_sync(0xffffffffu, v, 1);
                v += __shfl_xor_sync(0xffffffffu, v, 2);
                if (tig == 0) atomicAdd(&rsum[wm * 32 + mt * 16 + grp + p * 8], v);
            }
        __syncthreads();
        if (tid < 128) inv[tid] = 1.f / rsum[tid];
        __syncthreads();

        float acc[2][4][4] = {};
        #pragma unroll
        for (int ks = 0; ks < 4; ks++) {
            const unsigned kcB = (unsigned)ks * 32;
            unsigned ah0[4], ah1[4], al0[4], al1[4];
            lm4(ah0, QhU + aT0 + kcB); lm4(ah1, QhU + aT1 + kcB);
            lm4(al0, QlU + aT0 + kcB); lm4(al1, QlU + aT1 + kcB);
            unsigned bh0[4], bh1[4], bl0[4], bl1[4];
            lm4(bh0, kvhU + nb0 + kcB); lm4(bh1, kvhU + nb1 + kcB);
            lm4(bl0, kvlU + nb0 + kcB); lm4(bl1, kvlU + nb1 + kcB);
            mma_f16(acc[0][0], ah0, bh0);     mma_f16(acc[0][0], ah0, bl0);     mma_f16(acc[0][0], al0, bh0);
            mma_f16(acc[1][0], ah1, bh0);     mma_f16(acc[1][0], ah1, bl0);     mma_f16(acc[1][0], al1, bh0);
            mma_f16(acc[0][1], ah0, bh0 + 2); mma_f16(acc[0][1], ah0, bl0 + 2); mma_f16(acc[0][1], al0, bh0 + 2);
            mma_f16(acc[1][1], ah1, bh0 + 2); mma_f16(acc[1][1], ah1, bl0 + 2); mma_f16(acc[1][1], al1, bh0 + 2);
            mma_f16(acc[0][2], ah0, bh1);     mma_f16(acc[0][2], ah0, bl1);     mma_f16(acc[0][2], al0, bh1);
            mma_f16(acc[1][2], ah1, bh1);     mma_f16(acc[1][2], ah1, bl1);     mma_f16(acc[1][2], al1, bh1);
            mma_f16(acc[0][3], ah0, bh1 + 2); mma_f16(acc[0][3], ah0, bl1 + 2); mma_f16(acc[0][3], al0, bh1 + 2);
            mma_f16(acc[1][3], ah1, bh1 + 2); mma_f16(acc[1][3], ah1, bl1 + 2); mma_f16(acc[1][3], al1, bh1 + 2);
        }
        #pragma unroll
        for (int mt = 0; mt < 2; mt++)
            #pragma unroll
            for (int nt = 0; nt < 4; nt++) {
                const int r = wm * 32 + mt * 16 + grp;
                const int c = wn * 32 + nt * 8 + tig * 2;
                const float i0 = inv[r], i1 = inv[r + 8];
                __half* d0 = g_qkv + (size_t)(b * NN + n0 + r) * INNER + h * 64 + c;
                __half* d1 = g_qkv + (size_t)(b * NN + n0 + r + 8) * INNER + h * 64 + c;
                *(__half2*)d0 = __floats2half2_rn(acc[mt][nt][0] * i0, acc[mt][nt][1] * i0);
                *(__half2*)d1 = __floats2half2_rn(acc[mt][nt][2] * i1, acc[mt][nt][3] * i1);
            }
        __syncthreads();
    }
}

// ------------------------------------------------------------------------------
extern "C" void kernel_launch(void* const* d_in, const int* in_sizes, int n_in,
                              void* d_out, int out_size) {
    const float* x      = (const float*)d_in[0];
    const float* conv_w = (const float*)d_in[1];
    const float* conv_b = (const float*)d_in[2];
    const float* Wq     = (const float*)d_in[3];
    const float* Wk     = (const float*)d_in[4];
    const float* Wv     = (const float*)d_in[5];
    const float* W1     = (const float*)d_in[6];
    const float* b1     = (const float*)d_in[7];
    const float* W2     = (const float*)d_in[8];
    const float* b2     = (const float*)d_in[9];
    float* out = (float*)d_out;

    using EncFn = decltype(&cuTensorMapEncodeTiled);
    static EncFn enc = nullptr;
    if (!enc) {
        void* fp = nullptr;
        cudaDriverEntryPointQueryResult qr;
        cudaGetDriverEntryPointByVersion("cuTensorMapEncodeTiled", &fp, 12000,
                                         cudaEnableDefault, &qr);
        enc = (EncFn)fp;
    }
    static CUtensorMap mCA, mCB, mA0, mB0, mA1, mB1;
    {
        void *xp, *wp, *qkvp, *w1p, *h1p, *w2p;
        cudaGetSymbolAddress(&xp, g_xh);
        cudaGetSymbolAddress(&wp, g_wch);
        cudaGetSymbolAddress(&qkvp, g_qkv);
        cudaGetSymbolAddress(&w1p, g_w1h);
        cudaGetSymbolAddress(&h1p, g_h1);
        cudaGetSymbolAddress(&w2p, g_w2h);
        cuuint32_t e4[4] = {1, 1, 1, 1};
        cuuint64_t dA[4] = {256, 128, 128, 8};
        cuuint64_t sA[3] = {512, 65536, 8388608};
        cuuint32_t bA[4] = {64, 128, 1, 1};
        enc(&mCA, CU_TENSOR_MAP_DATA_TYPE_FLOAT16, 4, xp, dA, sA, bA, e4,
            CU_TENSOR_MAP_INTERLEAVE_NONE, CU_TENSOR_MAP_SWIZZLE_128B,
            CU_TENSOR_MAP_L2_PROMOTION_L2_128B, CU_TENSOR_MAP_FLOAT_OOB_FILL_NONE);
        cuuint64_t dB[2] = {KCONV, INNER};
        cuuint64_t sB[1] = {KCONV * 2};
        cuuint32_t bB[2] = {64, 128};
        enc(&mCB, CU_TENSOR_MAP_DATA_TYPE_FLOAT16, 2, wp, dB, sB, bB, e4,
            CU_TENSOR_MAP_INTERLEAVE_NONE, CU_TENSOR_MAP_SWIZZLE_128B,
            CU_TENSOR_MAP_L2_PROMOTION_L2_128B, CU_TENSOR_MAP_FLOAT_OOB_FILL_NONE);
        cuuint64_t dA0[2] = {512, 131072}; cuuint64_t sA0[1] = {1024};
        enc(&mA0, CU_TENSOR_MAP_DATA_TYPE_FLOAT16, 2, qkvp, dA0, sA0, bB, e4,
            CU_TENSOR_MAP_INTERLEAVE_NONE, CU_TENSOR_MAP_SWIZZLE_128B,
            CU_TENSOR_MAP_L2_PROMOTION_L2_128B, CU_TENSOR_MAP_FLOAT_OOB_FILL_NONE);
        cuuint64_t dB0[2] = {512, 256}; cuuint64_t sB0[1] = {1024};
        enc(&mB0, CU_TENSOR_MAP_DATA_TYPE_FLOAT16, 2, w1p, dB0, sB0, bB, e4,
            CU_TENSOR_MAP_INTERLEAVE_NONE, CU_TENSOR_MAP_SWIZZLE_128B,
            CU_TENSOR_MAP_L2_PROMOTION_L2_128B, CU_TENSOR_MAP_FLOAT_OOB_FILL_NONE);
        cuuint64_t dA1[2] = {256, 131072}; cuuint64_t sA1[1] = {512};
        enc(&mA1, CU_TENSOR_MAP_DATA_TYPE_FLOAT16, 2, h1p, dA1, sA1, bB, e4,
            CU_TENSOR_MAP_INTERLEAVE_NONE, CU_TENSOR_MAP_SWIZZLE_128B,
            CU_TENSOR_MAP_L2_PROMOTION_L2_128B, CU_TENSOR_MAP_FLOAT_OOB_FILL_NONE);
        cuuint64_t dB1[2] = {256, 256}; cuuint64_t sB1[1] = {512};
        enc(&mB1, CU_TENSOR_MAP_DATA_TYPE_FLOAT16, 2, w2p, dB1, sB1, bB, e4,
            CU_TENSOR_MAP_INTERLEAVE_NONE, CU_TENSOR_MAP_SWIZZLE_128B,
            CU_TENSOR_MAP_L2_PROMOTION_L2_128B, CU_TENSOR_MAP_FLOAT_OOB_FILL_NONE);
    }

    cudaFuncSetAttribute(k_conv, cudaFuncAttributeMaxDynamicSharedMemorySize, 66560);
    cudaFuncSetAttribute(k_mlp<0>, cudaFuncAttributeMaxDynamicSharedMemorySize, 66560);
    cudaFuncSetAttribute(k_mlp<1>, cudaFuncAttributeMaxDynamicSharedMemorySize, 66560);
    cudaFuncSetAttribute(k_kv,   cudaFuncAttributeMaxDynamicSharedMemorySize, 92160);
    cudaFuncSetAttribute(k_qkv,  cudaFuncAttributeMaxDynamicSharedMemorySize, 93184);

    k_prep<<<(BB * NN * CC) / 4 / 256, 256>>>(x, conv_w, W1, W2, Wq, Wk, Wv);
    k_conv<<<dim3(INNER / 128, (BB * NN) / 128), 256, 66560>>>(mCA, mCB, conv_b);
    k_kv<<<dim3(8, BB * HEADS), 256, 92160>>>();
    k_kvnorm<<<(BB * HEADS * KRR * DHH) / 256, 256>>>();
    k_qkv<<<dim3(32, BB * HEADS), 256, 93184>>>();
    k_mlp<0><<<dim3(CC / 128, (BB * NN) / 128), 256, 66560>>>(mA0, mB0, b1, nullptr);
    k_mlp<1><<<dim3(CC / 128, (BB * NN) / 128), 256, 66560>>>(mA1, mB1, b2, out);
}

// round 17
// speedup vs baseline: 1.1819x; 1.0316x over previous
#include <cuda_runtime.h>
#include <cuda.h>
#include <cuda_fp16.h>
#include <math.h>

#define BB 8
#define CC 256
#define NN 16384
#define HEADS 8
#define INNER 512
#define KCONV 2304
#define KRR 64
#define DHH 64

__device__ __half g_wch[(size_t)INNER * KCONV];
__device__ __half g_xh[(size_t)BB * NN * CC];
__device__ __half g_w1h[CC * INNER];
__device__ __half g_w2h[CC * CC];
__device__ __half g_xc[(size_t)BB * NN * INNER];
__device__ float  g_colsum[BB * HEADS * KRR];
__device__ float  g_kv[BB * HEADS * KRR * DHH];
__device__ __half g_qkv[(size_t)BB * NN * INNER];
__device__ __half g_h1[(size_t)BB * NN * CC];
__device__ __half g_wqh[4096], g_wql[4096], g_wkh[4096], g_wkl[4096];
__device__ __half g_wvh[4096], g_wvl[4096];
__device__ __half g_kvth[64 * 4096], g_kvtl[64 * 4096];   // [bh][dh][kr]

__device__ __forceinline__ void mma_f16(float c[4], const unsigned a[4], const unsigned b[2]) {
    asm volatile("mma.sync.aligned.m16n8k16.row.col.f32.f16.f16.f32 "
        "{%0,%1,%2,%3}, {%4,%5,%6,%7}, {%8,%9}, {%0,%1,%2,%3};"
        : "+f"(c[0]), "+f"(c[1]), "+f"(c[2]), "+f"(c[3])
        : "r"(a[0]), "r"(a[1]), "r"(a[2]), "r"(a[3]), "r"(b[0]), "r"(b[1]));
}
__device__ __forceinline__ void lm4(unsigned r[4], unsigned a) {
    asm volatile("ldmatrix.sync.aligned.m8n8.x4.shared.b16 {%0,%1,%2,%3}, [%4];"
        : "=r"(r[0]), "=r"(r[1]), "=r"(r[2]), "=r"(r[3]) : "r"(a));
}
__device__ __forceinline__ void split_h(float f, __half& hi, __half& lo) {
    hi = __float2half_rn(f);
    lo = __float2half_rn(f - __half2float(hi));
}
__device__ __forceinline__ unsigned smem_u32(const void* p) {
    return (unsigned)__cvta_generic_to_shared(p);
}
__device__ __forceinline__ void mb_init(unsigned a, unsigned n) {
    asm volatile("mbarrier.init.shared.b64 [%0], %1;" :: "r"(a), "r"(n) : "memory");
}
__device__ __forceinline__ void mb_expect(unsigned a, unsigned bytes) {
    asm volatile("mbarrier.arrive.expect_tx.shared.b64 _, [%0], %1;"
                 :: "r"(a), "r"(bytes) : "memory");
}
__device__ __forceinline__ void mb_arrive(unsigned a) {
    asm volatile("mbarrier.arrive.shared.b64 _, [%0];" :: "r"(a) : "memory");
}
__device__ __forceinline__ void mb_wait(unsigned a, unsigned ph) {
    asm volatile("{\n\t.reg .pred P;\n\tW%=:\n\t"
                 "mbarrier.try_wait.parity.shared.b64 P, [%0], %1;\n\t"
                 "@!P bra W%=;\n\t}" :: "r"(a), "r"(ph) : "memory");
}
__device__ __forceinline__ void tma4d(unsigned dst, const CUtensorMap* m,
                                      int c0, int c1, int c2, int c3, unsigned mb) {
    asm volatile("cp.async.bulk.tensor.4d.shared::cta.global.tile.mbarrier::complete_tx::bytes"
                 " [%0], [%1, {%2,%3,%4,%5}], [%6];"
                 :: "r"(dst), "l"(m), "r"(c0), "r"(c1), "r"(c2), "r"(c3), "r"(mb) : "memory");
}
__device__ __forceinline__ void tma2d(unsigned dst, const CUtensorMap* m,
                                      int c0, int c1, unsigned mb) {
    asm volatile("cp.async.bulk.tensor.2d.shared::cta.global.tile.mbarrier::complete_tx::bytes"
                 " [%0], [%1, {%2,%3}], [%4];"
                 :: "r"(dst), "l"(m), "r"(c0), "r"(c1), "r"(mb) : "memory");
}

// ---------------- fused prep (grid covers ALL of x: 8388608 float4s) ------------
__global__ void k_prep(const float* __restrict__ x, const float* __restrict__ conv_w,
                       const float* __restrict__ W1, const float* __restrict__ W2,
                       const float* __restrict__ Wq, const float* __restrict__ Wk,
                       const float* __restrict__ Wv) {
    int t = blockIdx.x * 256 + threadIdx.x;
    float4 v = ((const float4*)x)[t];
    ((__half2*)g_xh)[t * 2]     = __floats2half2_rn(v.x, v.y);
    ((__half2*)g_xh)[t * 2 + 1] = __floats2half2_rn(v.z, v.w);
    if (t < INNER * KCONV) {
        int o = t / KCONV, k = t - o * KCONV;
        g_wch[t] = __float2half_rn(conv_w[(size_t)(o * CC + (k & 255)) * 9 + (k >> 8)]);
    }
    if (t < BB * HEADS * KRR * DHH) g_kv[t] = 0.f;
    if (t < CC * INNER) g_w1h[t] = __float2half_rn(W1[t]);
    if (t < CC * CC)    g_w2h[t] = __float2half_rn(W2[t]);
    if (t < BB * HEADS * KRR) g_colsum[t] = 0.f;
    if (t < 4096) {
        split_h(Wq[t], g_wqh[t], g_wql[t]);
        split_h(Wk[t], g_wkh[t], g_wkl[t]);
        split_h(Wv[t], g_wvh[t], g_wvl[t]);
    }
}

// ---------------- conv: fp16 mma + ldmatrix, TMA 2-buf, empty-barrier pipe ------
__global__ __launch_bounds__(256, 2) void k_conv(
    const __grid_constant__ CUtensorMap mA,
    const __grid_constant__ CUtensorMap mB,
    const float* __restrict__ conv_b) {
    extern __shared__ __align__(1024) char smc[];
    const unsigned sbase = smem_u32(smc);
    const int tid = threadIdx.x, lane = tid & 31, wid = tid >> 5;
    const int wm = wid & 3, wn = wid >> 2;
    const int grp = lane >> 2, tig = lane & 3;
    const int otile = blockIdx.x * 128, mtile = blockIdx.y * 128;
    const int b = mtile >> 14;
    const int py = (mtile & (NN - 1)) >> 7;

    if (tid == 0) {
        mb_init(sbase, 1);       mb_init(sbase + 8, 1);        // full[0..1]
        mb_init(sbase + 16, 256); mb_init(sbase + 24, 256);    // empty[0..1]
    }
    __syncthreads();

    const int a_r = (lane & 7) + ((lane >> 3) & 1) * 8;
    const unsigned a_kb = (lane >> 4) * 16;
    const unsigned axor = (unsigned)(a_r & 7) << 4;
    const int b_r = (lane & 7) + (lane >> 4) * 8;
    const unsigned b_kb = ((lane >> 3) & 1) * 16;
    const unsigned bxor = (unsigned)(b_r & 7) << 4;
    const unsigned Abase0 = sbase + 1024;
    const unsigned Bbase0 = sbase + 33792;

    float acc[2][8][4] = {};

    auto issue = [&](int s) {
        const int p = s & 1;
        const int g = s >> 2;
        const int dy = g / 3 - 1, dx = g % 3 - 1;
        const int cb = (s & 3) * 64;
        mb_expect(sbase + p * 8, 32768);
        tma4d(Abase0 + p * 16384, &mA, cb, dx, py + dy, b, sbase + p * 8);
        tma2d(Bbase0 + p * 16384, &mB, g * 256 + cb, otile, sbase + p * 8);
    };

    if (tid == 0) { issue(0); issue(1); }
    for (int s = 0; s < 36; s++) {
        const int p = s & 1;
        mb_wait(sbase + p * 8, (s >> 1) & 1);
        const unsigned Ab = Abase0 + p * 16384;
        const unsigned Bb = Bbase0 + p * 16384;
        #pragma unroll
        for (int ks = 0; ks < 4; ks++) {
            const unsigned ak = ((unsigned)(ks * 32) + a_kb) ^ axor;
            const unsigned bk = ((unsigned)(ks * 32) + b_kb) ^ bxor;
            unsigned a0[4], a1[4];
            lm4(a0, Ab + (unsigned)(wm * 32 + a_r) * 128 + ak);
            lm4(a1, Ab + (unsigned)(wm * 32 + 16 + a_r) * 128 + ak);
            #pragma unroll
            for (int np = 0; np < 4; np++) {
                unsigned bb[4];
                lm4(bb, Bb + (unsigned)(wn * 64 + np * 16 + b_r) * 128 + bk);
                mma_f16(acc[0][np * 2],     a0, bb);
                mma_f16(acc[1][np * 2],     a1, bb);
                mma_f16(acc[0][np * 2 + 1], a0, bb + 2);
                mma_f16(acc[1][np * 2 + 1], a1, bb + 2);
            }
        }
        mb_arrive(sbase + 16 + p * 8);
        if (s + 2 < 36 && tid == 0) {
            mb_wait(sbase + 16 + p * 8, (s >> 1) & 1);
            issue(s + 2);
        }
    }
    #pragma unroll
    for (int mt = 0; mt < 2; mt++)
        #pragma unroll
        for (int nt = 0; nt < 8; nt++) {
            const int r = wm * 32 + mt * 16 + grp;
            const int c = wn * 64 + nt * 8 + tig * 2;
            const float b0 = conv_b[otile + c], b1 = conv_b[otile + c + 1];
            *(__half2*)(g_xc + (size_t)(mtile + r) * INNER + otile + c) =
                __floats2half2_rn(acc[mt][nt][0] + b0, acc[mt][nt][1] + b1);
            *(__half2*)(g_xc + (size_t)(mtile + r + 8) * INNER + otile + c) =
                __floats2half2_rn(acc[mt][nt][2] + b0, acc[mt][nt][3] + b1);
        }
}

// ---------------- MLP: fp16 mma + ldmatrix, TMA 2-buf, empty-barrier pipe -------
template <int MODE>
__global__ __launch_bounds__(256, 2) void k_mlp(
    const __grid_constant__ CUtensorMap mA,
    const __grid_constant__ CUtensorMap mB,
    const float* __restrict__ bias,
    float* __restrict__ out_ext) {
    constexpr int K = MODE ? CC : INNER;
    constexpr int NS = K / 64;
    extern __shared__ __align__(1024) char smc[];
    const unsigned sbase = smem_u32(smc);
    const int tid = threadIdx.x, lane = tid & 31, wid = tid >> 5;
    const int wm = wid & 3, wn = wid >> 2;
    const int grp = lane >> 2, tig = lane & 3;
    const int otile = blockIdx.x * 128, m0 = blockIdx.y * 128;

    if (tid == 0) {
        mb_init(sbase, 1);        mb_init(sbase + 8, 1);
        mb_init(sbase + 16, 256); mb_init(sbase + 24, 256);
    }
    __syncthreads();

    const int a_r = (lane & 7) + ((lane >> 3) & 1) * 8;
    const unsigned a_kb = (lane >> 4) * 16;
    const unsigned axor = (unsigned)(a_r & 7) << 4;
    const int b_r = (lane & 7) + (lane >> 4) * 8;
    const unsigned b_kb = ((lane >> 3) & 1) * 16;
    const unsigned bxor = (unsigned)(b_r & 7) << 4;
    const unsigned Abase0 = sbase + 1024;
    const unsigned Bbase0 = sbase + 33792;

    float acc[2][8][4] = {};

    auto issue = [&](int s) {
        const int p = s & 1;
        mb_expect(sbase + p * 8, 32768);
        tma2d(Abase0 + p * 16384, &mA, s * 64, m0, sbase + p * 8);
        tma2d(Bbase0 + p * 16384, &mB, s * 64, otile, sbase + p * 8);
    };

    if (tid == 0) { issue(0); if (NS > 1) issue(1); }
    for (int s = 0; s < NS; s++) {
        const int p = s & 1;
        mb_wait(sbase + p * 8, (s >> 1) & 1);
        const unsigned Ab = Abase0 + p * 16384;
        const unsigned Bb = Bbase0 + p * 16384;
        #pragma unroll
        for (int ks = 0; ks < 4; ks++) {
            const unsigned ak = ((unsigned)(ks * 32) + a_kb) ^ axor;
            const unsigned bk = ((unsigned)(ks * 32) + b_kb) ^ bxor;
            unsigned a0[4], a1[4];
            lm4(a0, Ab + (unsigned)(wm * 32 + a_r) * 128 + ak);
            lm4(a1, Ab + (unsigned)(wm * 32 + 16 + a_r) * 128 + ak);
            #pragma unroll
            for (int np = 0; np < 4; np++) {
                unsigned bb[4];
                lm4(bb, Bb + (unsigned)(wn * 64 + np * 16 + b_r) * 128 + bk);
                mma_f16(acc[0][np * 2],     a0, bb);
                mma_f16(acc[1][np * 2],     a1, bb);
                mma_f16(acc[0][np * 2 + 1], a0, bb + 2);
                mma_f16(acc[1][np * 2 + 1], a1, bb + 2);
            }
        }
        mb_arrive(sbase + 16 + p * 8);
        if (s + 2 < NS && tid == 0) {
            mb_wait(sbase + 16 + p * 8, (s >> 1) & 1);
            issue(s + 2);
        }
    }
    #pragma unroll
    for (int mt = 0; mt < 2; mt++)
        #pragma unroll
        for (int nt = 0; nt < 8; nt++) {
            const int r = wm * 32 + mt * 16 + grp;
            const int c = wn * 64 + nt * 8 + tig * 2;
            const float b0 = bias[otile + c], b1 = bias[otile + c + 1];
            float v[4] = {acc[mt][nt][0] + b0, acc[mt][nt][1] + b1,
                          acc[mt][nt][2] + b0, acc[mt][nt][3] + b1};
            if (MODE == 0) {
                #pragma unroll
                for (int j = 0; j < 4; j++)
                    v[j] = 0.5f * v[j] * (1.0f + erff(v[j] * 0.70710678118654752f));
                *(__half2*)(g_h1 + (size_t)(m0 + r) * CC + otile + c) =
                    __floats2half2_rn(v[0], v[1]);
                *(__half2*)(g_h1 + (size_t)(m0 + r + 8) * CC + otile + c) =
                    __floats2half2_rn(v[2], v[3]);
            } else {
                *(float2*)(out_ext + (size_t)(m0 + r) * CC + otile + c) =
                    make_float2(v[0], v[1]);
                *(float2*)(out_ext + (size_t)(m0 + r + 8) * CC + otile + c) =
                    make_float2(v[2], v[3]);
            }
        }
}

// ---------------- k_kv: fp16 split mma, ldmatrix, double-buffered X ------------
__global__ __launch_bounds__(256) void k_kv() {
    extern __shared__ __half sh[];
    __half *Xs0 = sh, *Xs1 = sh + 4608;
    __half *Wkh = sh + 9216,  *Wkl = sh + 13824;
    __half *Wvh = sh + 18432, *Wvl = sh + 23040;
    __half *Kth = sh + 27648, *Ktl = sh + 32256;
    __half *Vth = sh + 36864, *Vtl = sh + 41472;

    const int tid = threadIdx.x, lane = tid & 31, wid = tid >> 5;
    const int wm = wid & 3, wn = wid >> 2;
    const int grp = lane >> 2, tig = lane & 3;
    const int bh = blockIdx.y, b = bh >> 3, h = bh & 7;
    const int r = tid >> 2, c0 = (tid & 3) * 16;

    {
        const int gsrc = r * 64 + c0;
        const int sdst = r * 72 + c0;
        *(uint4*)&Wkh[sdst]     = *(const uint4*)&g_wkh[gsrc];
        *(uint4*)&Wkh[sdst + 8] = *(const uint4*)&g_wkh[gsrc + 8];
        *(uint4*)&Wkl[sdst]     = *(const uint4*)&g_wkl[gsrc];
        *(uint4*)&Wkl[sdst + 8] = *(const uint4*)&g_wkl[gsrc + 8];
        *(uint4*)&Wvh[sdst]     = *(const uint4*)&g_wvh[gsrc];
        *(uint4*)&Wvh[sdst + 8] = *(const uint4*)&g_wvh[gsrc + 8];
        *(uint4*)&Wvl[sdst]     = *(const uint4*)&g_wvl[gsrc];
        *(uint4*)&Wvl[sdst + 8] = *(const uint4*)&g_wvl[gsrc + 8];
    }

    const int la_r = (lane & 7) + ((lane >> 3) & 1) * 8;
    const unsigned a_off = (unsigned)la_r * 144 + (lane >> 4) * 16;
    const int lb_r = (lane & 7) + (lane >> 4) * 8;
    const unsigned b_off = (unsigned)lb_r * 144 + ((lane >> 3) & 1) * 16;
    const unsigned Xs0U = smem_u32(Xs0);
    const unsigned WkhU = smem_u32(Wkh), WklU = smem_u32(Wkl);
    const unsigned WvhU = smem_u32(Wvh), WvlU = smem_u32(Wvl);
    const unsigned KthU = smem_u32(Kth), KtlU = smem_u32(Ktl);
    const unsigned VthU = smem_u32(Vth), VtlU = smem_u32(Vtl);
    const unsigned aTile = (unsigned)(wm * 16) * 144 + a_off;
    const unsigned nb0 = (unsigned)(wn * 32) * 144 + b_off;
    const unsigned nb1 = nb0 + 16u * 144;

    float kvacc[4][4] = {};
    float csum[8] = {};
    const int mrow = wm * 16 + grp;

    for (int ch = 0; ch < 32; ch++) {
        const int n0 = blockIdx.x * 2048 + ch * 64;
        __half* Xc = (ch & 1) ? Xs1 : Xs0;
        {
            const __half* xsrc = g_xc + (size_t)(b * NN + n0 + r) * INNER + h * 64 + c0;
            *(uint4*)&Xc[r * 72 + c0]     = *(const uint4*)xsrc;
            *(uint4*)&Xc[r * 72 + c0 + 8] = *(const uint4*)(xsrc + 8);
        }
        __syncthreads();

        const unsigned XcU = Xs0U + (unsigned)(ch & 1) * 9216;
        float ka[4][4] = {}, va[4][4] = {};
        #pragma unroll
        for (int ks = 0; ks < 4; ks++) {
            const unsigned kcB = (unsigned)ks * 32;
            unsigned a[4];
            lm4(a, XcU + aTile + kcB);
            unsigned kh0[4], kh1[4], kl0[4], kl1[4];
            unsigned vh0[4], vh1[4], vl0[4], vl1[4];
            lm4(kh0, WkhU + nb0 + kcB); lm4(kh1, WkhU + nb1 + kcB);
            lm4(kl0, WklU + nb0 + kcB); lm4(kl1, WklU + nb1 + kcB);
            lm4(vh0, WvhU + nb0 + kcB); lm4(vh1, WvhU + nb1 + kcB);
            lm4(vl0, WvlU + nb0 + kcB); lm4(vl1, WvlU + nb1 + kcB);
            mma_f16(ka[0], a, kh0);     mma_f16(ka[0], a, kl0);
            mma_f16(ka[1], a, kh0 + 2); mma_f16(ka[1], a, kl0 + 2);
            mma_f16(ka[2], a, kh1);     mma_f16(ka[2], a, kl1);
            mma_f16(ka[3], a, kh1 + 2); mma_f16(ka[3], a, kl1 + 2);
            mma_f16(va[0], a, vh0);     mma_f16(va[0], a, vl0);
            mma_f16(va[1], a, vh0 + 2); mma_f16(va[1], a, vl0 + 2);
            mma_f16(va[2], a, vh1);     mma_f16(va[2], a, vl1);
            mma_f16(va[3], a, vh1 + 2); mma_f16(va[3], a, vl1 + 2);
        }
        #pragma unroll
        for (int nt = 0; nt < 4; nt++) {
            const int c = wn * 32 + nt * 8 + tig * 2;
            float e;
            e = __expf(ka[nt][0]); csum[nt*2]   += e; split_h(e, Kth[c*72+mrow],       Ktl[c*72+mrow]);
            e = __expf(ka[nt][1]); csum[nt*2+1] += e; split_h(e, Kth[(c+1)*72+mrow],   Ktl[(c+1)*72+mrow]);
            e = __expf(ka[nt][2]); csum[nt*2]   += e; split_h(e, Kth[c*72+mrow+8],     Ktl[c*72+mrow+8]);
            e = __expf(ka[nt][3]); csum[nt*2+1] += e; split_h(e, Kth[(c+1)*72+mrow+8], Ktl[(c+1)*72+mrow+8]);
            split_h(va[nt][0], Vth[c*72+mrow],       Vtl[c*72+mrow]);
            split_h(va[nt][1], Vth[(c+1)*72+mrow],   Vtl[(c+1)*72+mrow]);
            split_h(va[nt][2], Vth[c*72+mrow+8],     Vtl[c*72+mrow+8]);
            split_h(va[nt][3], Vth[(c+1)*72+mrow+8], Vtl[(c+1)*72+mrow+8]);
        }
        __syncthreads();

        #pragma unroll
        for (int ks = 0; ks < 4; ks++) {
            const unsigned kcB = (unsigned)ks * 32;
            unsigned ah[4], al[4];
            lm4(ah, KthU + aTile + kcB);
            lm4(al, KtlU + aTile + kcB);
            unsigned bh0[4], bh1[4], bl0[4], bl1[4];
            lm4(bh0, VthU + nb0 + kcB); lm4(bh1, VthU + nb1 + kcB);
            lm4(bl0, VtlU + nb0 + kcB); lm4(bl1, VtlU + nb1 + kcB);
            mma_f16(kvacc[0], ah, bh0);     mma_f16(kvacc[0], ah, bl0);     mma_f16(kvacc[0], al, bh0);
            mma_f16(kvacc[1], ah, bh0 + 2); mma_f16(kvacc[1], ah, bl0 + 2); mma_f16(kvacc[1], al, bh0 + 2);
            mma_f16(kvacc[2], ah, bh1);     mma_f16(kvacc[2], ah, bl1);     mma_f16(kvacc[2], al, bh1);
            mma_f16(kvacc[3], ah, bh1 + 2); mma_f16(kvacc[3], ah, bl1 + 2); mma_f16(kvacc[3], al, bh1 + 2);
        }
    }

    float* kvbase = g_kv + (size_t)bh * (KRR * DHH);
    #pragma unroll
    for (int nt = 0; nt < 4; nt++) {
        const int c = wn * 32 + nt * 8 + tig * 2;
        atomicAdd(kvbase + mrow * 64 + c,           kvacc[nt][0]);
        atomicAdd(kvbase + mrow * 64 + c + 1,       kvacc[nt][1]);
        atomicAdd(kvbase + (mrow + 8) * 64 + c,     kvacc[nt][2]);
        atomicAdd(kvbase + (mrow + 8) * 64 + c + 1, kvacc[nt][3]);
    }
    #pragma unroll
    for (int idx = 0; idx < 8; idx++) {
        const int c = wn * 32 + (idx >> 1) * 8 + tig * 2 + (idx & 1);
        atomicAdd(g_colsum + bh * 64 + c, csum[idx]);
    }
}

// ---------------- kv normalize + transpose + split ------------------------------
__global__ void k_kvnorm() {
    int i = blockIdx.x * 256 + threadIdx.x;
    float v = g_kv[i] / g_colsum[i >> 6];
    int bh = i >> 12, kr = (i >> 6) & 63, dh = i & 63;
    __half hi, lo;
    split_h(v, hi, lo);
    int o = bh * 4096 + dh * 64 + kr;
    g_kvth[o] = hi;
    g_kvtl[o] = lo;
}

// ---------------- k_qkv: 4 chunks/block, setup amortized ------------------------
__global__ __launch_bounds__(256) void k_qkv() {
    extern __shared__ __half sh[];
    __half *Xs   = sh;
    __half *Qh   = sh + 9216,  *Ql  = sh + 18432;
    __half *Wqh  = sh + 27648, *Wql = sh + 32256;
    __half *kvth = sh + 36864, *kvtl = sh + 41472;
    float  *rsum = (float*)(sh + 46080);
    float  *inv  = rsum + 128;

    const int tid = threadIdx.x, lane = tid & 31, wid = tid >> 5;
    const int wm = wid & 3, wn = wid >> 2;
    const int grp = lane >> 2, tig = lane & 3;
    const int bh = blockIdx.y, b = bh >> 3, h = bh & 7;

    {
        const int r = tid >> 2, c0 = (tid & 3) * 16;
        const int gsrc = r * 64 + c0;
        const int sdst = r * 72 + c0;
        *(uint4*)&Wqh[sdst]     = *(const uint4*)&g_wqh[gsrc];
        *(uint4*)&Wqh[sdst + 8] = *(const uint4*)&g_wqh[gsrc + 8];
        *(uint4*)&Wql[sdst]     = *(const uint4*)&g_wql[gsrc];
        *(uint4*)&Wql[sdst + 8] = *(const uint4*)&g_wql[gsrc + 8];
        const __half* kvh = g_kvth + bh * 4096 + gsrc;
        const __half* kvl = g_kvtl + bh * 4096 + gsrc;
        *(uint4*)&kvth[sdst]     = *(const uint4*)kvh;
        *(uint4*)&kvth[sdst + 8] = *(const uint4*)(kvh + 8);
        *(uint4*)&kvtl[sdst]     = *(const uint4*)kvl;
        *(uint4*)&kvtl[sdst + 8] = *(const uint4*)(kvl + 8);
    }

    const int la_r = (lane & 7) + ((lane >> 3) & 1) * 8;
    const unsigned a_off = (unsigned)la_r * 144 + (lane >> 4) * 16;
    const int lb_r = (lane & 7) + (lane >> 4) * 8;
    const unsigned b_off = (unsigned)lb_r * 144 + ((lane >> 3) & 1) * 16;
    const unsigned XsU = smem_u32(Xs), QhU = smem_u32(Qh), QlU = smem_u32(Ql);
    const unsigned WqhU = smem_u32(Wqh), WqlU = smem_u32(Wql);
    const unsigned kvhU = smem_u32(kvth), kvlU = smem_u32(kvtl);
    const unsigned aT0 = (unsigned)(wm * 32) * 144 + a_off;
    const unsigned aT1 = aT0 + 16u * 144;
    const unsigned nb0 = (unsigned)(wn * 32) * 144 + b_off;
    const unsigned nb1 = nb0 + 16u * 144;
    const int xr = tid >> 1, xc0 = (tid & 1) * 32;

    for (int cch = 0; cch < 4; cch++) {
        const int n0 = blockIdx.x * 512 + cch * 128;
        {
            const __half* xsrc = g_xc + (size_t)(b * NN + n0 + xr) * INNER + h * 64 + xc0;
            #pragma unroll
            for (int j = 0; j < 4; j++)
                *(uint4*)&Xs[xr * 72 + xc0 + j * 8] = *(const uint4*)(xsrc + j * 8);
        }
        if (tid < 128) rsum[tid] = 0.f;
        __syncthreads();

        float qa[2][4][4] = {};
        #pragma unroll
        for (int ks = 0; ks < 4; ks++) {
            const unsigned kcB = (unsigned)ks * 32;
            unsigned a0[4], a1[4];
            lm4(a0, XsU + aT0 + kcB);
            lm4(a1, XsU + aT1 + kcB);
            unsigned qh0[4], qh1[4], ql0[4], ql1[4];
            lm4(qh0, WqhU + nb0 + kcB); lm4(qh1, WqhU + nb1 + kcB);
            lm4(ql0, WqlU + nb0 + kcB); lm4(ql1, WqlU + nb1 + kcB);
            mma_f16(qa[0][0], a0, qh0);     mma_f16(qa[0][0], a0, ql0);
            mma_f16(qa[1][0], a1, qh0);     mma_f16(qa[1][0], a1, ql0);
            mma_f16(qa[0][1], a0, qh0 + 2); mma_f16(qa[0][1], a0, ql0 + 2);
            mma_f16(qa[1][1], a1, qh0 + 2); mma_f16(qa[1][1], a1, ql0 + 2);
            mma_f16(qa[0][2], a0, qh1);     mma_f16(qa[0][2], a0, ql1);
            mma_f16(qa[1][2], a1, qh1);     mma_f16(qa[1][2], a1, ql1);
            mma_f16(qa[0][3], a0, qh1 + 2); mma_f16(qa[0][3], a0, ql1 + 2);
            mma_f16(qa[1][3], a1, qh1 + 2); mma_f16(qa[1][3], a1, ql1 + 2);
        }
        float rp[2][2] = {};
        #pragma unroll
        for (int mt = 0; mt < 2; mt++)
            #pragma unroll
            for (int nt = 0; nt < 4; nt++) {
                const int r = wm * 32 + mt * 16 + grp;
                const int c = wn * 32 + nt * 8 + tig * 2;
                float e0 = __expf(qa[mt][nt][0]), e1 = __expf(qa[mt][nt][1]);
                float e2 = __expf(qa[mt][nt][2]), e3 = __expf(qa[mt][nt][3]);
                rp[mt][0] += e0 + e1; rp[mt][1] += e2 + e3;
                __half h0, l0, h1, l1;
                split_h(e0, h0, l0); split_h(e1, h1, l1);
                *(__half2*)&Qh[r * 72 + c] = __halves2half2(h0, h1);
                *(__half2*)&Ql[r * 72 + c] = __halves2half2(l0, l1);
                split_h(e2, h0, l0); split_h(e3, h1, l1);
                *(__half2*)&Qh[(r + 8) * 72 + c] = __halves2half2(h0, h1);
                *(__half2*)&Ql[(r + 8) * 72 + c] = __halves2half2(l0, l1);
            }
        #pragma unroll
        for (int mt = 0; mt < 2; mt++)
            #pragma unroll
            for (int p = 0; p < 2; p++) {
                float v = rp[mt][p];
                v += __shfl_xor_sync(0xffffffffu, v, 1);
                v += __shfl_xor_sync(0xffffffffu, v, 2);
                if (tig == 0) atomicAdd(&rsum[wm * 32 + mt * 16 + grp + p * 8], v);
            }
        __syncthreads();
        if (tid < 128) inv[tid] = 1.f / rsum[tid];
        __syncthreads();

        float acc[2][4][4] = {};
        #pragma unroll
        for (int ks = 0; ks < 4; ks++) {
            const unsigned kcB = (unsigned)ks * 32;
            unsigned ah0[4], ah1[4], al0[4], al1[4];
            lm4(ah0, QhU + aT0 + kcB); lm4(ah1, QhU + aT1 + kcB);
            lm4(al0, QlU + aT0 + kcB); lm4(al1, QlU + aT1 + kcB);
            unsigned bh0[4], bh1[4], bl0[4], bl1[4];
            lm4(bh0, kvhU + nb0 + kcB); lm4(bh1, kvhU + nb1 + kcB);
            lm4(bl0, kvlU + nb0 + kcB); lm4(bl1, kvlU + nb1 + kcB);
            mma_f16(acc[0][0], ah0, bh0);     mma_f16(acc[0][0], ah0, bl0);     mma_f16(acc[0][0], al0, bh0);
            mma_f16(acc[1][0], ah1, bh0);     mma_f16(acc[1][0], ah1, bl0);     mma_f16(acc[1][0], al1, bh0);
            mma_f16(acc[0][1], ah0, bh0 + 2); mma_f16(acc[0][1], ah0, bl0 + 2); mma_f16(acc[0][1], al0, bh0 + 2);
            mma_f16(acc[1][1], ah1, bh0 + 2); mma_f16(acc[1][1], ah1, bl0 + 2); mma_f16(acc[1][1], al1, bh0 + 2);
            mma_f16(acc[0][2], ah0, bh1);     mma_f16(acc[0][2], ah0, bl1);     mma_f16(acc[0][2], al0, bh1);
            mma_f16(acc[1][2], ah1, bh1);     mma_f16(acc[1][2], ah1, bl1);     mma_f16(acc[1][2], al1, bh1);
            mma_f16(acc[0][3], ah0, bh1 + 2); mma_f16(acc[0][3], ah0, bl1 + 2); mma_f16(acc[0][3], al0, bh1 + 2);
            mma_f16(acc[1][3], ah1, bh1 + 2); mma_f16(acc[1][3], ah1, bl1 + 2); mma_f16(acc[1][3], al1, bh1 + 2);
        }
        #pragma unroll
        for (int mt = 0; mt < 2; mt++)
            #pragma unroll
            for (int nt = 0; nt < 4; nt++) {
                const int r = wm * 32 + mt * 16 + grp;
                const int c = wn * 32 + nt * 8 + tig * 2;
                const float i0 = inv[r], i1 = inv[r + 8];
                __half* d0 = g_qkv + (size_t)(b * NN + n0 + r) * INNER + h * 64 + c;
                __half* d1 = g_qkv + (size_t)(b * NN + n0 + r + 8) * INNER + h * 64 + c;
                *(__half2*)d0 = __floats2half2_rn(acc[mt][nt][0] * i0, acc[mt][nt][1] * i0);
                *(__half2*)d1 = __floats2half2_rn(acc[mt][nt][2] * i1, acc[mt][nt][3] * i1);
            }
        __syncthreads();
    }
}

// ------------------------------------------------------------------------------
extern "C" void kernel_launch(void* const* d_in, const int* in_sizes, int n_in,
                              void* d_out, int out_size) {
    const float* x      = (const float*)d_in[0];
    const float* conv_w = (const float*)d_in[1];
    const float* conv_b = (const float*)d_in[2];
    const float* Wq     = (const float*)d_in[3];
    const float* Wk     = (const float*)d_in[4];
    const float* Wv     = (const float*)d_in[5];
    const float* W1     = (const float*)d_in[6];
    const float* b1     = (const float*)d_in[7];
    const float* W2     = (const float*)d_in[8];
    const float* b2     = (const float*)d_in[9];
    float* out = (float*)d_out;

    using EncFn = decltype(&cuTensorMapEncodeTiled);
    static EncFn enc = nullptr;
    if (!enc) {
        void* fp = nullptr;
        cudaDriverEntryPointQueryResult qr;
        cudaGetDriverEntryPointByVersion("cuTensorMapEncodeTiled", &fp, 12000,
                                         cudaEnableDefault, &qr);
        enc = (EncFn)fp;
    }
    static CUtensorMap mCA, mCB, mA0, mB0, mA1, mB1;
    {
        void *xp, *wp, *qkvp, *w1p, *h1p, *w2p;
        cudaGetSymbolAddress(&xp, g_xh);
        cudaGetSymbolAddress(&wp, g_wch);
        cudaGetSymbolAddress(&qkvp, g_qkv);
        cudaGetSymbolAddress(&w1p, g_w1h);
        cudaGetSymbolAddress(&h1p, g_h1);
        cudaGetSymbolAddress(&w2p, g_w2h);
        cuuint32_t e4[4] = {1, 1, 1, 1};
        cuuint64_t dA[4] = {256, 128, 128, 8};
        cuuint64_t sA[3] = {512, 65536, 8388608};
        cuuint32_t bA[4] = {64, 128, 1, 1};
        enc(&mCA, CU_TENSOR_MAP_DATA_TYPE_FLOAT16, 4, xp, dA, sA, bA, e4,
            CU_TENSOR_MAP_INTERLEAVE_NONE, CU_TENSOR_MAP_SWIZZLE_128B,
            CU_TENSOR_MAP_L2_PROMOTION_L2_128B, CU_TENSOR_MAP_FLOAT_OOB_FILL_NONE);
        cuuint64_t dB[2] = {KCONV, INNER};
        cuuint64_t sB[1] = {KCONV * 2};
        cuuint32_t bB[2] = {64, 128};
        enc(&mCB, CU_TENSOR_MAP_DATA_TYPE_FLOAT16, 2, wp, dB, sB, bB, e4,
            CU_TENSOR_MAP_INTERLEAVE_NONE, CU_TENSOR_MAP_SWIZZLE_128B,
            CU_TENSOR_MAP_L2_PROMOTION_L2_128B, CU_TENSOR_MAP_FLOAT_OOB_FILL_NONE);
        cuuint64_t dA0[2] = {512, 131072}; cuuint64_t sA0[1] = {1024};
        enc(&mA0, CU_TENSOR_MAP_DATA_TYPE_FLOAT16, 2, qkvp, dA0, sA0, bB, e4,
            CU_TENSOR_MAP_INTERLEAVE_NONE, CU_TENSOR_MAP_SWIZZLE_128B,
            CU_TENSOR_MAP_L2_PROMOTION_L2_128B, CU_TENSOR_MAP_FLOAT_OOB_FILL_NONE);
        cuuint64_t dB0[2] = {512, 256}; cuuint64_t sB0[1] = {1024};
        enc(&mB0, CU_TENSOR_MAP_DATA_TYPE_FLOAT16, 2, w1p, dB0, sB0, bB, e4,
            CU_TENSOR_MAP_INTERLEAVE_NONE, CU_TENSOR_MAP_SWIZZLE_128B,
            CU_TENSOR_MAP_L2_PROMOTION_L2_128B, CU_TENSOR_MAP_FLOAT_OOB_FILL_NONE);
        cuuint64_t dA1[2] = {256, 131072}; cuuint64_t sA1[1] = {512};
        enc(&mA1, CU_TENSOR_MAP_DATA_TYPE_FLOAT16, 2, h1p, dA1, sA1, bB, e4,
            CU_TENSOR_MAP_INTERLEAVE_NONE, CU_TENSOR_MAP_SWIZZLE_128B,
            CU_TENSOR_MAP_L2_PROMOTION_L2_128B, CU_TENSOR_MAP_FLOAT_OOB_FILL_NONE);
        cuuint64_t dB1[2] = {256, 256}; cuuint64_t sB1[1] = {512};
        enc(&mB1, CU_TENSOR_MAP_DATA_TYPE_FLOAT16, 2, w2p, dB1, sB1, bB, e4,
            CU_TENSOR_MAP_INTERLEAVE_NONE, CU_TENSOR_MAP_SWIZZLE_128B,
            CU_TENSOR_MAP_L2_PROMOTION_L2_128B, CU_TENSOR_MAP_FLOAT_OOB_FILL_NONE);
    }

    cudaFuncSetAttribute(k_conv, cudaFuncAttributeMaxDynamicSharedMemorySize, 66560);
    cudaFuncSetAttribute(k_mlp<0>, cudaFuncAttributeMaxDynamicSharedMemorySize, 66560);
    cudaFuncSetAttribute(k_mlp<1>, cudaFuncAttributeMaxDynamicSharedMemorySize, 66560);
    cudaFuncSetAttribute(k_kv,   cudaFuncAttributeMaxDynamicSharedMemorySize, 92160);
    cudaFuncSetAttribute(k_qkv,  cudaFuncAttributeMaxDynamicSharedMemorySize, 93184);

    k_prep<<<(BB * NN * CC) / 4 / 256, 256>>>(x, conv_w, W1, W2, Wq, Wk, Wv);
    k_conv<<<dim3(INNER / 128, (BB * NN) / 128), 256, 66560>>>(mCA, mCB, conv_b);
    k_kv<<<dim3(8, BB * HEADS), 256, 92160>>>();
    k_kvnorm<<<(BB * HEADS * KRR * DHH) / 256, 256>>>();
    k_qkv<<<dim3(32, BB * HEADS), 256, 93184>>>();
    k_mlp<0><<<dim3(CC / 128, (BB * NN) / 128), 256, 66560>>>(mA0, mB0, b1, nullptr);
    k_mlp<1><<<dim3(CC / 128, (BB * NN) / 128), 256, 66560>>>(mA1, mB1, b2, out);
}